// round 11
// baseline (speedup 1.0000x reference)
#include <cuda_runtime.h>
#include <cuda_bf16.h>
#include <math.h>
#include <stdint.h>

// ---------------- problem constants ----------------
#define BB    256
#define SS    512
#define DS    64
#define DF    300
#define C2    600
#define NPASS 4
#define NTOK  (BB*SS)

// ---------------- refine tiling (tf32 mma.sync m16n8k8) ----------------
#define T_TOK 64
#define THR   512
#define NWARP 16
#define NT1   42
#define NS1   38
#define NT2   19
#define NS2   75
#define LDB1  72
#define WSLOT (NT1*128)
#define SZ1   (WSLOT*4)
#define SZ2   (NT2*128*4)
#define NPREP (NS1*NT1 + NS2*NT2)   // 3021

// smem float offsets (X region time-aliased: sB1 -> sH -> dfeat)
#define OFF_X    0
#define OFF_SW   (OFF_X + 600*LDB1)
#define OFF_SC1  (OFF_SW + 2*WSLOT)
#define OFF_SU1  (OFF_SC1 + C2)
#define OFF_SV1  (OFF_SU1 + C2)
#define OFF_SBMU (OFF_SV1 + C2)
#define OFF_SB2  (OFF_SBMU + DS)
#define OFF_SA   (OFF_SB2 + DF)
#define OFF_SM2  (OFF_SA  + T_TOK)
#define OFF_MBAR (OFF_SM2 + T_TOK)
#define SMEM_FLOATS (OFF_MBAR + 8)
#define SMEM_BYTES  (SMEM_FLOATS * 4)

// ---------------- persistent scratch ----------------
__device__ float g_mu   [NTOK * DS];
__device__ float g_ivar [NTOK * DS];
__device__ float g_alpha[NTOK];
__device__ float g_feat [NTOK * DF];
__device__ float g_w    [NTOK];
__device__ float g_winv [BB];
__device__ float g_meaning[BB * DF];
__device__ float g_c1  [BB * C2];
__device__ float g_cmu [BB * DS];
__device__ float g_cgate[BB];
__device__ float g_csum [BB];
__device__ float g_csum2[BB];
__device__ float g_u1  [C2];
__device__ float g_v1  [C2];
__device__ __align__(16) float g_W1f[NS1 * NT1 * 128];
__device__ __align__(16) float g_W2f[NS2 * NT2 * 128];

__device__ __forceinline__ float sigmoidf_(float x) { return 1.0f / (1.0f + expf(-x)); }
__device__ __forceinline__ float warp_red(float x) {
    #pragma unroll
    for (int o = 16; o; o >>= 1) x += __shfl_xor_sync(0xffffffffu, x, o);
    return x;
}
__device__ __forceinline__ float tf32r(float x) {
    uint32_t u;
    asm("cvt.rna.tf32.f32 %0, %1;" : "=r"(u) : "f"(x));
    return __uint_as_float(u);
}
__device__ __forceinline__ void mma_tf32(float* d, uint4 a, uint32_t b0, uint32_t b1) {
    asm volatile(
        "mma.sync.aligned.m16n8k8.row.col.f32.tf32.tf32.f32 "
        "{%0,%1,%2,%3}, {%4,%5,%6,%7}, {%8,%9}, {%0,%1,%2,%3};"
        : "+f"(d[0]), "+f"(d[1]), "+f"(d[2]), "+f"(d[3])
        : "r"(a.x), "r"(a.y), "r"(a.z), "r"(a.w), "r"(b0), "r"(b1));
}
#define MBAR_INIT(mbar_u32, cnt) \
    asm volatile("mbarrier.init.shared.b64 [%0], %1;" :: "r"(mbar_u32), "r"(cnt) : "memory")
#define MBAR_EXPECT_TX(mbar_u32, bytes) \
    asm volatile("mbarrier.arrive.expect_tx.shared.b64 _, [%0], %1;" :: "r"(mbar_u32), "r"(bytes) : "memory")
#define BULK_CP(dst_u32, src_ptr, nbytes, mbar_u32) \
    asm volatile("cp.async.bulk.shared::cluster.global.mbarrier::complete_tx::bytes [%0], [%1], %2, [%3];" \
        :: "r"(dst_u32), "l"(src_ptr), "r"(nbytes), "r"(mbar_u32) : "memory")
__device__ __forceinline__ void mbar_wait(uint32_t mbar, uint32_t parity) {
    asm volatile(
        "{\n\t.reg .pred P;\n\t"
        "WL%=:\n\t"
        "mbarrier.try_wait.parity.acquire.cta.shared::cta.b64 P, [%0], %1, 0x989680;\n\t"
        "@P bra WD%=;\n\t"
        "bra WL%=;\n\t"
        "WD%=:\n\t}"
        :: "r"(mbar), "r"(parity) : "memory");
}
#define NBAR_SYNC(id, cnt)   asm volatile("bar.sync %0, %1;"   :: "r"(id), "r"(cnt) : "memory")
#define NBAR_ARRIVE(id, cnt) asm volatile("bar.arrive %0, %1;" :: "r"(id), "r"(cnt) : "memory")

// ---------------- K1: init tokens + weight-fragment prep + u1/v1 (grid-split) ----------------
__global__ void __launch_bounds__(128) k_init_prep(int init_blocks, int p,
                       const int* __restrict__ ids,
                       const float* __restrict__ mu_t,
                       const float* __restrict__ lv_t,
                       const float* __restrict__ a_t,
                       const float* __restrict__ f_t,
                       const float* __restrict__ pos_mu,
                       const float* __restrict__ pos_alpha,
                       const float* __restrict__ W1all,
                       const float* __restrict__ lng,
                       const float* __restrict__ lnb,
                       const float* __restrict__ b1,
                       const float* __restrict__ muWall,
                       const float* __restrict__ W2all)
{
    __shared__ float pu[4], pv[4];
    int blk = blockIdx.x;
    int tid = threadIdx.x;     // 128

    if (blk < init_blocks) {
        // ---- token init ----
        int i = blk;
        int s = i & (SS - 1);
        int id = ids[i];
        if (tid < 64) {
            g_mu  [i * DS + tid] = mu_t[id * DS + tid] + pos_mu[s * DS + tid];
            g_ivar[i * DS + tid] = expf(-lv_t[id * DS + tid]);
        }
        for (int f = tid; f < DF; f += 128)
            g_feat[i * DF + f] = f_t[id * DF + f];
        if (tid == 0)
            g_alpha[i] = sigmoidf_(a_t[id]) * sigmoidf_(pos_alpha[s]);
        return;
    }
    int pb = blk - init_blocks;
    if (pb < NPREP) {
        // ---- fragment prep ----
        int lane = tid >> 2, v = tid & 3;
        int rq = lane >> 2, kq = lane & 3;
        if (pb < NS1 * NT1) {
            int s = pb / NT1, t = pb - s * NT1;
            int r = t * 16 + rq + (v & 1) * 8;
            int k = s * 8 + kq + (v >> 1) * 4;
            float val = 0.f;
            if (k < DF) {
                if (r < C2)
                    val = W1all[(size_t)p * C2 * C2 + (size_t)r * C2 + k] * lng[p * C2 + k];
                else if (r < C2 + DS)
                    val = muWall[(size_t)p * DS * C2 + (size_t)(r - C2) * C2 + k];
            }
            g_W1f[(size_t)pb * 128 + tid] = tf32r(val);
        } else {
            int b2 = pb - NS1 * NT1;
            int s = b2 / NT2, t = b2 - s * NT2;
            int r = t * 16 + rq + (v & 1) * 8;
            int k = s * 8 + kq + (v >> 1) * 4;
            float val = 0.f;
            if (r < DF)
                val = W2all[(size_t)p * DF * C2 + (size_t)r * C2 + k];
            g_W2f[(size_t)b2 * 128 + tid] = tf32r(val);
        }
        return;
    }
    // ---- u1/v1 for h ----
    {
        int h = pb - NPREP;
        const float* row = W1all + (size_t)p * C2 * C2 + (size_t)h * C2;
        const float* g   = lng + p * C2;
        const float* bb  = lnb + p * C2;
        float u = 0.f, v = 0.f;
        for (int c = tid; c < C2; c += 128) {
            float w = row[c];
            u += w * g[c];
            v += w * bb[c];
        }
        u = warp_red(u); v = warp_red(v);
        int warp = tid >> 5, lane = tid & 31;
        if (lane == 0) { pu[warp] = u; pv[warp] = v; }
        __syncthreads();
        if (tid == 0) {
            g_u1[h] = pu[0] + pu[1] + pu[2] + pu[3];
            g_v1[h] = pv[0] + pv[1] + pv[2] + pv[3] + b1[p * C2 + h];
        }
    }
}

// ---------------- K2: centroid + gaussian weights ----------------
__global__ void __launch_bounds__(256) k_weights(const float* __restrict__ log_tau)
{
    __shared__ __align__(16) float cent[DS];
    __shared__ float part[4][DS];
    __shared__ float red[8];

    int b = blockIdx.x, tid = threadIdx.x, base = b * SS;

    {
        int d = tid & 63, gq = tid >> 6;
        const float* mp = g_mu + (size_t)(base + gq * 128) * DS + d;
        float a0 = 0.f, a1 = 0.f;
        #pragma unroll 8
        for (int i = 0; i < 64; i++) {
            a0 += mp[i * DS];
            a1 += mp[(i + 64) * DS];
        }
        part[gq][d] = a0 + a1;
    }
    __syncthreads();
    if (tid < DS)
        cent[tid] = (part[0][tid] + part[1][tid] + part[2][tid] + part[3][tid]) * (1.0f / SS);
    __syncthreads();

    float nh_invtau = -0.5f / expf(log_tau[0]);
    float wpart = 0.f;
    for (int s = tid; s < SS; s += 256) {
        const float4* mu4 = (const float4*)(g_mu   + (size_t)(base + s) * DS);
        const float4* iv4 = (const float4*)(g_ivar + (size_t)(base + s) * DS);
        const float4* c4  = (const float4*)cent;
        float d2 = 0.f;
        #pragma unroll
        for (int q = 0; q < 16; q++) {
            float4 m = mu4[q], v = iv4[q], c = c4[q];
            float dx = c.x - m.x; d2 += dx * dx * v.x;
            float dy = c.y - m.y; d2 += dy * dy * v.y;
            float dz = c.z - m.z; d2 += dz * dz * v.z;
            float dw = c.w - m.w; d2 += dw * dw * v.w;
        }
        float w = g_alpha[base + s] * expf(nh_invtau * d2);
        g_w[base + s] = w;
        wpart += w;
    }
    float t = warp_red(wpart);
    if ((tid & 31) == 0) red[tid >> 5] = t;
    __syncthreads();
    if (tid == 0) {
        float x = 0.f;
        #pragma unroll
        for (int i = 0; i < 8; i++) x += red[i];
        g_winv[b] = 1.0f / (x + 1e-8f);
    }
}

// ---------------- K3: per-b meaning + context projections (merged) ----------------
__global__ void __launch_bounds__(256) k_meaning_ctx(int p,
                                             const float* __restrict__ W1all,
                                             const float* __restrict__ lng,
                                             const float* __restrict__ muWall,
                                             const float* __restrict__ gWall,
                                             float* __restrict__ out_final,
                                             int write_final, int do_ctx)
{
    __shared__ float wv[SS];
    __shared__ float mvec[DF];
    __shared__ float gm[DF];
    int b = blockIdx.x, tid = threadIdx.x;
    int warp = tid >> 5, lane = tid & 31;

    for (int s = tid; s < SS; s += 256) wv[s] = g_w[b * SS + s];
    __syncthreads();

    float winv = g_winv[b];
    if (tid < 150) {
        const float2* f2 = (const float2*)(g_feat + (size_t)b * SS * DF) + tid;
        float a0 = 0.f, a1 = 0.f;
        #pragma unroll 8
        for (int s = 0; s < SS; s++) {
            float2 v = f2[(size_t)s * 150];
            float ww = wv[s];
            a0 += ww * v.x; a1 += ww * v.y;
        }
        a0 *= winv; a1 *= winv;
        mvec[2 * tid] = a0; mvec[2 * tid + 1] = a1;
        float* dst = write_final ? out_final : g_meaning;
        dst[b * DF + 2 * tid] = a0;
        dst[b * DF + 2 * tid + 1] = a1;
    }
    if (!do_ctx) return;
    __syncthreads();

    const float* g = lng + p * C2 + DF;
    for (int c = tid; c < DF; c += 256) gm[c] = g[c] * mvec[c];
    __syncthreads();

    // c1[b][h]
    const float* W = W1all + (size_t)p * C2 * C2 + DF;
    for (int h = warp; h < C2; h += 8) {
        float acc = 0.f;
        const float* r = W + (size_t)h * C2;
        for (int c = lane; c < DF; c += 32) acc += r[c] * gm[c];
        acc = warp_red(acc);
        if (lane == 0) g_c1[b * C2 + h] = acc;
    }
    // cmu
    const float* Wm = muWall + (size_t)p * DS * C2;
    for (int d = warp; d < DS; d += 8) {
        float acc = 0.f;
        const float* r = Wm + (size_t)d * C2 + DF;
        for (int c = lane; c < DF; c += 32) acc += r[c] * mvec[c];
        acc = warp_red(acc);
        if (lane == 0) g_cmu[b * DS + d] = acc;
    }
    if (warp == 0) {
        const float* gw = gWall + p * C2 + DF;
        float acc = 0.f;
        for (int c = lane; c < DF; c += 32) acc += gw[c] * mvec[c];
        acc = warp_red(acc);
        if (lane == 0) g_cgate[b] = acc;
    }
    if (warp == 1) {
        float s1 = 0.f, s2 = 0.f;
        for (int c = lane; c < DF; c += 32) { float v = mvec[c]; s1 += v; s2 += v * v; }
        s1 = warp_red(s1); s2 = warp_red(s2);
        if (lane == 0) { g_csum[b] = s1; g_csum2[b] = s2; }
    }
}

// ---------------- K4: refinement — decoupled named-barrier pipeline ----------------
__global__ void __launch_bounds__(THR, 1) k_refine(int p,
    const float* __restrict__ mubAll,
    const float* __restrict__ gWall, const float* __restrict__ gbAll,
    const float* __restrict__ b2All)
{
    extern __shared__ float sm[];
    float* sX   = sm + OFF_X;
    float* sW   = sm + OFF_SW;
    float* sC1  = sm + OFF_SC1;
    float* sU1  = sm + OFF_SU1;
    float* sV1  = sm + OFF_SV1;
    float* sBmu = sm + OFF_SBMU;
    float* sB2  = sm + OFF_SB2;
    float* sA   = sm + OFF_SA;
    float* sM2  = sm + OFF_SM2;
    const uint32_t* sXu = (const uint32_t*)sX;

    int b   = blockIdx.y;
    int s0  = blockIdx.x * T_TOK;
    int tid = threadIdx.x;
    int tokBase = b * SS + s0;
    int w = tid >> 5, lane = tid & 31;
    int kq = lane & 3, rq = lane >> 2;

    uint32_t smem_u32 = (uint32_t)__cvta_generic_to_shared(sm);
    uint32_t sw_u32[2] = { smem_u32 + OFF_SW * 4,
                           smem_u32 + (OFF_SW + WSLOT) * 4 };
    uint32_t mb = smem_u32 + OFF_MBAR * 4;

    if (tid == 0) {
        #pragma unroll
        for (int i = 0; i < 4; i++) MBAR_INIT(mb + 8 * i, 1);
        asm volatile("fence.proxy.async.shared::cta;" ::: "memory");
    }
    __syncthreads();

    if (tid == 0) {
        MBAR_EXPECT_TX(mb, SZ1);
        BULK_CP(sw_u32[0], g_W1f, SZ1, mb);
    }

    for (int i = tid; i < C2; i += THR) {
        sC1[i] = g_c1[b * C2 + i];
        sU1[i] = g_u1[i];
        sV1[i] = g_v1[i];
    }
    if (tid < DS)  sBmu[tid] = mubAll[p * DS + tid] + g_cmu[b * DS + tid];
    if (tid >= THR - DF) sB2[tid - (THR - DF)] = b2All[p * DF + (tid - (THR - DF))];

    for (int idx = tid; idx < DF * T_TOK; idx += THR) {
        int t = idx / DF;
        int f = idx - t * DF;
        sX[f * LDB1 + t] = tf32r(g_feat[(size_t)(tokBase + t) * DF + f]);
    }
    for (int idx = tid; idx < 4 * LDB1; idx += THR) sX[DF * LDB1 + idx] = 0.f;
    __syncthreads();

    // ---- per-token LN stats + alpha gate ----
    {
        float csum = g_csum[b], csum2 = g_csum2[b], cgate = g_cgate[b];
        const float* gw = gWall + p * C2;
        float gbv = gbAll[p];
        #pragma unroll
        for (int tt = 0; tt < 4; tt++) {
            int t = w * 4 + tt;
            float s1 = 0.f, s2 = 0.f, gd = 0.f;
            for (int k = lane; k < DF; k += 32) {
                float v = sX[k * LDB1 + t];
                s1 += v; s2 += v * v; gd += gw[k] * v;
            }
            s1 = warp_red(s1); s2 = warp_red(s2); gd = warp_red(gd);
            if (lane == 0) {
                float mean = (s1 + csum) * (1.0f / C2);
                float var  = (s2 + csum2) * (1.0f / C2) - mean * mean;
                float rstd = rsqrtf(var + 1e-5f);
                sA[t]  = rstd;
                sM2[t] = -mean * rstd;
                g_alpha[tokBase + t] *= sigmoidf_(gd + cgate + gbv);
            }
        }
    }

    // ================= GEMM1: [672 x 304] @ [304 x 64] =================
    float acc[3][32];
    #pragma unroll
    for (int i = 0; i < 3; i++)
        #pragma unroll
        for (int j = 0; j < 32; j++) acc[i][j] = 0.f;

    for (int s = 0; s < NS1; s++) {
        int k0 = s * 8;
        // B fragments: panel-independent -> load before the wait
        uint32_t bb0[8], bb1[8];
        #pragma unroll
        for (int nl = 0; nl < 8; nl++) {
            int n = nl * 8 + rq;
            bb0[nl] = sXu[(k0 + kq)     * LDB1 + n];
            bb1[nl] = sXu[(k0 + kq + 4) * LDB1 + n];
        }
        if (w == 0) {
            if (s >= 1 && s + 1 < NS1) NBAR_SYNC(1 + ((s + 1) & 1), THR);
            if (tid == 0 && s + 1 < NS1) {
                uint32_t m = mb + 8 * ((s + 1) & 1);
                MBAR_EXPECT_TX(m, SZ1);
                BULK_CP(sw_u32[(s + 1) & 1], g_W1f + (size_t)(s + 1) * WSLOT, SZ1, m);
            }
        }
        mbar_wait(mb + 8 * (s & 1), (s >> 1) & 1);

        const float* swb = sW + (s & 1) * WSLOT;
        #pragma unroll
        for (int i = 0; i < 3; i++) {
            int tile = w + NWARP * i;
            if (tile < NT1) {
                uint4 aa = *(const uint4*)(swb + tile * 128 + lane * 4);
                #pragma unroll
                for (int nl = 0; nl < 8; nl++)
                    mma_tf32(&acc[i][nl * 4], aa, bb0[nl], bb1[nl]);
            }
        }
        if (w != 0 && s < NS1 - 2) NBAR_ARRIVE(1 + (s & 1), THR);
    }
    __syncthreads();   // all GEMM1 reads done before epilogue rewrites sX

    // prefetch GEMM2 panel 0 (overlaps epilogue)
    if (tid == 0) {
        MBAR_EXPECT_TX(mb + 16, SZ2);
        BULK_CP(sw_u32[0], g_W2f, SZ2, mb + 16);
    }

    // ---- GEMM1 epilogue: LN/GELU -> sH ; mu rows -> tanh -> g_mu ----
    #pragma unroll
    for (int i = 0; i < 3; i++) {
        int tile = w + NWARP * i;
        if (tile < NT1) {
            int m0 = tile * 16;
            #pragma unroll
            for (int half = 0; half < 2; half++) {
                int r = m0 + rq + half * 8;
                if (r < C2) {
                    float c1v = sC1[r], u1v = sU1[r], v1v = sV1[r];
                    #pragma unroll
                    for (int hb = 0; hb < 2; hb++)
                        #pragma unroll
                        for (int nl = 0; nl < 4; nl++)
                            #pragma unroll
                            for (int q = 0; q < 2; q++) {
                                int n = (hb * 4 + nl) * 8 + 2 * kq + q;
                                float a = acc[i][hb * 16 + nl * 4 + half * 2 + q];
                                float x = sA[n] * (a + c1v) + sM2[n] * u1v + v1v;
                                float gl = 0.5f * x * (1.0f + erff(x * 0.70710678118654752f));
                                sX[r * LDB1 + n] = tf32r(gl);
                            }
                } else if (r < C2 + DS) {
                    int d = r - C2;
                    float bm = sBmu[d];
                    #pragma unroll
                    for (int hb = 0; hb < 2; hb++)
                        #pragma unroll
                        for (int nl = 0; nl < 4; nl++)
                            #pragma unroll
                            for (int q = 0; q < 2; q++) {
                                int n = (hb * 4 + nl) * 8 + 2 * kq + q;
                                float a = acc[i][hb * 16 + nl * 4 + half * 2 + q];
                                g_mu[(size_t)(tokBase + n) * DS + d] += tanhf(a + bm);
                            }
                }
            }
        }
    }
    __syncthreads();   // sH fully written before GEMM2 B reads

    // ================= GEMM2: [304 x 600] @ [600 x 64] =================
    float ac2[2][32];
    #pragma unroll
    for (int i = 0; i < 2; i++)
        #pragma unroll
        for (int j = 0; j < 32; j++) ac2[i][j] = 0.f;

    for (int s = 0; s < NS2; s++) {
        int k0 = s * 8;
        uint32_t bb0[8], bb1[8];
        #pragma unroll
        for (int nl = 0; nl < 8; nl++) {
            int n = nl * 8 + rq;
            bb0[nl] = sXu[(k0 + kq)     * LDB1 + n];
            bb1[nl] = sXu[(k0 + kq + 4) * LDB1 + n];
        }
        if (w == 0) {
            if (s >= 1 && s + 1 < NS2) NBAR_SYNC(3 + ((s + 1) & 1), THR);
            if (tid == 0 && s + 1 < NS2) {
                uint32_t m = mb + 16 + 8 * ((s + 1) & 1);
                MBAR_EXPECT_TX(m, SZ2);
                BULK_CP(sw_u32[(s + 1) & 1], g_W2f + (size_t)(s + 1) * (NT2 * 128), SZ2, m);
            }
        }
        mbar_wait(mb + 16 + 8 * (s & 1), (s >> 1) & 1);

        const float* swb = sW + (s & 1) * WSLOT;
        #pragma unroll
        for (int i = 0; i < 2; i++) {
            int tile = w + NWARP * i;
            if (tile < NT2) {
                uint4 aa = *(const uint4*)(swb + tile * 128 + lane * 4);
                #pragma unroll
                for (int nl = 0; nl < 8; nl++)
                    mma_tf32(&ac2[i][nl * 4], aa, bb0[nl], bb1[nl]);
            }
        }
        if (w != 0 && s < NS2 - 2) NBAR_ARRIVE(3 + (s & 1), THR);
    }
    __syncthreads();

    // ---- stage dfeat into sX (sH dead) ----
    #pragma unroll
    for (int i = 0; i < 2; i++) {
        int tile = w + NWARP * i;
        if (tile < NT2) {
            int m0 = tile * 16;
            #pragma unroll
            for (int half = 0; half < 2; half++) {
                int f = m0 + rq + half * 8;
                if (f < DF) {
                    #pragma unroll
                    for (int hb = 0; hb < 2; hb++)
                        #pragma unroll
                        for (int nl = 0; nl < 4; nl++)
                            #pragma unroll
                            for (int q = 0; q < 2; q++) {
                                int n = (hb * 4 + nl) * 8 + 2 * kq + q;
                                sX[f * LDB1 + n] = ac2[i][hb * 16 + nl * 4 + half * 2 + q];
                            }
                }
            }
        }
    }
    __syncthreads();

    // ---- coalesced residual writeback ----
    for (int idx = tid; idx < DF * T_TOK; idx += THR) {
        int t = idx / DF;
        int f = idx - t * DF;
        size_t a = (size_t)(tokBase + t) * DF + f;
        g_feat[a] = g_feat[a] + sX[f * LDB1 + t] + sB2[f];
    }
}

// ---------------- host launch ----------------
// Launch order: init+prep(1), weights(2), meaning_ctx(3), refine(4) <- ncu captures launch #4.
extern "C" void kernel_launch(void* const* d_in, const int* in_sizes, int n_in,
                              void* d_out, int out_size)
{
    const int*   ids     = (const int*)  d_in[0];
    const float* mu_t    = (const float*)d_in[2];
    const float* lv_t    = (const float*)d_in[3];
    const float* a_t     = (const float*)d_in[4];
    const float* f_t     = (const float*)d_in[5];
    const float* log_tau = (const float*)d_in[6];
    const float* pos_mu  = (const float*)d_in[7];
    const float* pos_a   = (const float*)d_in[8];
    const float* muW     = (const float*)d_in[9];
    const float* mub     = (const float*)d_in[10];
    const float* gW      = (const float*)d_in[11];
    const float* gb      = (const float*)d_in[12];
    const float* lng     = (const float*)d_in[13];
    const float* lnb     = (const float*)d_in[14];
    const float* W1      = (const float*)d_in[15];
    const float* b1      = (const float*)d_in[16];
    const float* W2      = (const float*)d_in[17];
    const float* b2      = (const float*)d_in[18];
    float* out = (float*)d_out;

    cudaFuncSetAttribute(k_refine, cudaFuncAttributeMaxDynamicSharedMemorySize, SMEM_BYTES);

    dim3 grid(SS / T_TOK, BB);
    for (int p = 0; p < NPASS - 1; p++) {
        int init_blocks = (p == 0) ? NTOK : 0;
        k_init_prep<<<init_blocks + NPREP + C2, 128>>>(init_blocks, p,
            ids, mu_t, lv_t, a_t, f_t, pos_mu, pos_a, W1, lng, lnb, b1, muW, W2);
        k_weights<<<BB, 256>>>(log_tau);
        k_meaning_ctx<<<BB, 256>>>(p, W1, lng, muW, gW, out, 0, 1);
        k_refine<<<grid, THR, SMEM_BYTES>>>(p, mub, gW, gb, b2);
    }
    k_weights<<<BB, 256>>>(log_tau);
    k_meaning_ctx<<<BB, 256>>>(0, W1, lng, muW, gW, out, 1, 0);
}

// round 12
// speedup vs baseline: 1.3618x; 1.3618x over previous
#include <cuda_runtime.h>
#include <cuda_bf16.h>
#include <math.h>
#include <stdint.h>

// ---------------- problem constants ----------------
#define BB    256
#define SS    512
#define DS    64
#define DF    300
#define C2    600
#define NPASS 4
#define NTOK  (BB*SS)

// ---------------- refine tiling (tf32 mma.sync m16n8k8) ----------------
#define T_TOK 64
#define THR   512
#define NWARP 16
#define NT1   42
#define NS1   38            // 8-k steps, GEMM1 (K=304)
#define NT2   19
#define NS2P  76            // 8-k steps, GEMM2 (K padded 600->608)
#define NP1   19            // 16-k panels GEMM1
#define NP2   38            // 16-k panels GEMM2
#define LDB1  72
#define PAN1  (2*NT1*128)   // 10752 floats / panel
#define PAN2  (2*NT2*128)   // 4864 floats / panel
#define SZP1  (PAN1*4)
#define SZP2  (PAN2*4)
#define NPREP (NS1*NT1 + NS2P*NT2)   // 3040

// smem float offsets. X region: rows 0..303 = B1 during GEMM1 (rows 304..607
// alias the GEMM1 weight double-buffer); later rows 0..607 = sH; then dfeat.
#define XROWS    608
#define OFF_X    0
#define OFF_W1A  (304*LDB1)          // 21888 (inside X, dead rows during GEMM1)
#define OFF_W1B  (OFF_W1A + PAN1)    // 32640 (ends 43392 <= 43776)
#define OFF_SW2  (XROWS*LDB1)        // 43776 (static GEMM2 weight buffers)
#define OFF_SC1  (OFF_SW2 + 2*PAN2)
#define OFF_SU1  (OFF_SC1 + C2)
#define OFF_SV1  (OFF_SU1 + C2)
#define OFF_SBMU (OFF_SV1 + C2)
#define OFF_SB2  (OFF_SBMU + DS)
#define OFF_SA   (OFF_SB2 + DF)
#define OFF_SM2  (OFF_SA  + T_TOK)
#define OFF_MBAR (OFF_SM2 + T_TOK)
#define SMEM_FLOATS (OFF_MBAR + 8)
#define SMEM_BYTES  (SMEM_FLOATS * 4)   // 223216 B

// ---------------- persistent scratch ----------------
__device__ float g_mu   [NTOK * DS];
__device__ float g_ivar [NTOK * DS];
__device__ float g_alpha[NTOK];
__device__ float g_feat [NTOK * DF];
__device__ float g_w    [NTOK];
__device__ float g_winv [BB];
__device__ float g_meaning[BB * DF];
__device__ float g_c1  [BB * C2];
__device__ float g_cmu [BB * DS];
__device__ float g_cgate[BB];
__device__ float g_csum [BB];
__device__ float g_csum2[BB];
__device__ float g_u1  [C2];
__device__ float g_v1  [C2];
__device__ __align__(16) float g_W1f[NS1 * NT1 * 128];
__device__ __align__(16) float g_W2f[NS2P * NT2 * 128];

__device__ __forceinline__ float sigmoidf_(float x) { return 1.0f / (1.0f + expf(-x)); }
__device__ __forceinline__ float warp_red(float x) {
    #pragma unroll
    for (int o = 16; o; o >>= 1) x += __shfl_xor_sync(0xffffffffu, x, o);
    return x;
}
__device__ __forceinline__ float tf32r(float x) {
    uint32_t u;
    asm("cvt.rna.tf32.f32 %0, %1;" : "=r"(u) : "f"(x));
    return __uint_as_float(u);
}
__device__ __forceinline__ void mma_tf32(float* d, uint4 a, uint32_t b0, uint32_t b1) {
    asm volatile(
        "mma.sync.aligned.m16n8k8.row.col.f32.tf32.tf32.f32 "
        "{%0,%1,%2,%3}, {%4,%5,%6,%7}, {%8,%9}, {%0,%1,%2,%3};"
        : "+f"(d[0]), "+f"(d[1]), "+f"(d[2]), "+f"(d[3])
        : "r"(a.x), "r"(a.y), "r"(a.z), "r"(a.w), "r"(b0), "r"(b1));
}
#define MBAR_INIT(mbar_u32, cnt) \
    asm volatile("mbarrier.init.shared.b64 [%0], %1;" :: "r"(mbar_u32), "r"(cnt) : "memory")
#define MBAR_EXPECT_TX(mbar_u32, bytes) \
    asm volatile("mbarrier.arrive.expect_tx.shared.b64 _, [%0], %1;" :: "r"(mbar_u32), "r"(bytes) : "memory")
#define BULK_CP(dst_u32, src_ptr, nbytes, mbar_u32) \
    asm volatile("cp.async.bulk.shared::cluster.global.mbarrier::complete_tx::bytes [%0], [%1], %2, [%3];" \
        :: "r"(dst_u32), "l"(src_ptr), "r"(nbytes), "r"(mbar_u32) : "memory")
__device__ __forceinline__ void mbar_wait(uint32_t mbar, uint32_t parity) {
    asm volatile(
        "{\n\t.reg .pred P;\n\t"
        "WL%=:\n\t"
        "mbarrier.try_wait.parity.acquire.cta.shared::cta.b64 P, [%0], %1, 0x989680;\n\t"
        "@P bra WD%=;\n\t"
        "bra WL%=;\n\t"
        "WD%=:\n\t}"
        :: "r"(mbar), "r"(parity) : "memory");
}

// ---------------- K1: token init + weight-fragment prep + u1/v1 (grid-split) ----------------
__global__ void __launch_bounds__(128) k_init_prep(int init_blocks, int p,
                       const int* __restrict__ ids,
                       const float* __restrict__ mu_t,
                       const float* __restrict__ lv_t,
                       const float* __restrict__ a_t,
                       const float* __restrict__ f_t,
                       const float* __restrict__ pos_mu,
                       const float* __restrict__ pos_alpha,
                       const float* __restrict__ W1all,
                       const float* __restrict__ lng,
                       const float* __restrict__ lnb,
                       const float* __restrict__ b1,
                       const float* __restrict__ muWall,
                       const float* __restrict__ W2all)
{
    __shared__ float pu[4], pv[4];
    int blk = blockIdx.x;
    int tid = threadIdx.x;

    if (blk < init_blocks) {
        int i = blk;
        int s = i & (SS - 1);
        int id = ids[i];
        if (tid < 64) {
            g_mu  [i * DS + tid] = mu_t[id * DS + tid] + pos_mu[s * DS + tid];
            g_ivar[i * DS + tid] = expf(-lv_t[id * DS + tid]);
        }
        for (int f = tid; f < DF; f += 128)
            g_feat[i * DF + f] = f_t[id * DF + f];
        if (tid == 0)
            g_alpha[i] = sigmoidf_(a_t[id]) * sigmoidf_(pos_alpha[s]);
        return;
    }
    int pb = blk - init_blocks;
    if (pb < NPREP) {
        int lane = tid >> 2, v = tid & 3;
        int rq = lane >> 2, kq = lane & 3;
        if (pb < NS1 * NT1) {
            int s = pb / NT1, t = pb - s * NT1;
            int r = t * 16 + rq + (v & 1) * 8;
            int k = s * 8 + kq + (v >> 1) * 4;
            float val = 0.f;
            if (k < DF) {
                if (r < C2)
                    val = W1all[(size_t)p * C2 * C2 + (size_t)r * C2 + k] * lng[p * C2 + k];
                else if (r < C2 + DS)
                    val = muWall[(size_t)p * DS * C2 + (size_t)(r - C2) * C2 + k];
            }
            g_W1f[(size_t)pb * 128 + tid] = tf32r(val);
        } else {
            int b2 = pb - NS1 * NT1;
            int s = b2 / NT2, t = b2 - s * NT2;
            int r = t * 16 + rq + (v & 1) * 8;
            int k = s * 8 + kq + (v >> 1) * 4;
            float val = 0.f;
            if (r < DF && k < C2)
                val = W2all[(size_t)p * DF * C2 + (size_t)r * C2 + k];
            g_W2f[(size_t)b2 * 128 + tid] = tf32r(val);
        }
        return;
    }
    {
        int h = pb - NPREP;
        const float* row = W1all + (size_t)p * C2 * C2 + (size_t)h * C2;
        const float* g   = lng + p * C2;
        const float* bb  = lnb + p * C2;
        float u = 0.f, v = 0.f;
        for (int c = tid; c < C2; c += 128) {
            float w = row[c];
            u += w * g[c];
            v += w * bb[c];
        }
        u = warp_red(u); v = warp_red(v);
        int warp = tid >> 5, lane = tid & 31;
        if (lane == 0) { pu[warp] = u; pv[warp] = v; }
        __syncthreads();
        if (tid == 0) {
            g_u1[h] = pu[0] + pu[1] + pu[2] + pu[3];
            g_v1[h] = pv[0] + pv[1] + pv[2] + pv[3] + b1[p * C2 + h];
        }
    }
}

// ---------------- K2: merged render — centroid + weights + meaning (per-b) ----------------
__global__ void __launch_bounds__(512) k_render(const float* __restrict__ log_tau,
                                                float* __restrict__ out_final,
                                                int write_final)
{
    __shared__ __align__(16) float cent[DS];
    __shared__ float part[8][DS];
    __shared__ float wv[SS];
    __shared__ float red[16];
    __shared__ float s_inv;
    __shared__ float pm[2][DF];

    int b = blockIdx.x, tid = threadIdx.x, base = b * SS;
    int warp = tid >> 5, lane = tid & 31;

    // centroid: 8 groups x 64 rows each
    {
        int d = tid & 63, gq = tid >> 6;
        const float* mp = g_mu + (size_t)(base + gq * 64) * DS + d;
        float a0 = 0.f, a1 = 0.f;
        #pragma unroll 8
        for (int i = 0; i < 32; i++) {
            a0 += mp[i * DS];
            a1 += mp[(i + 32) * DS];
        }
        part[gq][d] = a0 + a1;
    }
    __syncthreads();
    if (tid < DS) {
        float c = 0.f;
        #pragma unroll
        for (int i = 0; i < 8; i++) c += part[i][tid];
        cent[tid] = c * (1.0f / SS);
    }
    __syncthreads();

    // gaussian weights: one s per thread
    float nh_invtau = -0.5f / expf(log_tau[0]);
    {
        int s = tid;
        const float4* mu4 = (const float4*)(g_mu   + (size_t)(base + s) * DS);
        const float4* iv4 = (const float4*)(g_ivar + (size_t)(base + s) * DS);
        const float4* c4  = (const float4*)cent;
        float d2 = 0.f;
        #pragma unroll
        for (int q = 0; q < 16; q++) {
            float4 m = mu4[q], v = iv4[q], c = c4[q];
            float dx = c.x - m.x; d2 += dx * dx * v.x;
            float dy = c.y - m.y; d2 += dy * dy * v.y;
            float dz = c.z - m.z; d2 += dz * dz * v.z;
            float dw = c.w - m.w; d2 += dw * dw * v.w;
        }
        float w = g_alpha[base + s] * expf(nh_invtau * d2);
        wv[s] = w;
        float t = warp_red(w);
        if (lane == 0) red[warp] = t;
    }
    __syncthreads();
    if (tid == 0) {
        float x = 0.f;
        #pragma unroll
        for (int i = 0; i < 16; i++) x += red[i];
        s_inv = 1.0f / (x + 1e-8f);
    }
    __syncthreads();

    // meaning: 2 s-halves x 150 float2-threads, coalesced rows
    {
        int g = tid >> 8, t = tid & 255;
        if (t < 150) {
            const float2* f2 = (const float2*)(g_feat + (size_t)base * DF) + t
                               + (size_t)(g * 256) * 150;
            const float* wp = wv + g * 256;
            float a0 = 0.f, a1 = 0.f;
            #pragma unroll 8
            for (int s = 0; s < 256; s++) {
                float2 v = f2[(size_t)s * 150];
                float ww = wp[s];
                a0 += ww * v.x; a1 += ww * v.y;
            }
            pm[g][2 * t]     = a0;
            pm[g][2 * t + 1] = a1;
        }
    }
    __syncthreads();
    if (tid < DF) {
        float* dst = write_final ? out_final : g_meaning;
        dst[b * DF + tid] = (pm[0][tid] + pm[1][tid]) * s_inv;
    }
}

// ---------------- K3: context — tiled c1 GEMM + per-b cmu/gate/sums ----------------
__global__ void __launch_bounds__(256) k_ctx(int p,
                                             const float* __restrict__ W1all,
                                             const float* __restrict__ lng,
                                             const float* __restrict__ muWall,
                                             const float* __restrict__ gWall)
{
    __shared__ float shm[300 * 32];
    int blk = blockIdx.x;
    int tid = threadIdx.x;
    int warp = tid >> 5, lane = tid & 31;

    if (blk < 152) {
        float (*gmT)[32] = (float (*)[32])shm;
        int hbase = (blk >> 3) * 32;
        int bbase = (blk & 7) * 32;
        const float* g = lng + p * C2 + DF;
        for (int idx = tid; idx < 300 * 32; idx += 256) {
            int c = idx >> 5, bc = idx & 31;
            gmT[c][bc] = g[c] * g_meaning[(size_t)(bbase + bc) * DF + c];
        }
        __syncthreads();

        int h0 = hbase + warp;
        const float* W = W1all + (size_t)p * C2 * C2 + DF;
        const float4* r0 = (const float4*)(W + (size_t)(h0)      * C2);
        const float4* r1 = (const float4*)(W + (size_t)(h0 + 8)  * C2);
        const float4* r2 = (const float4*)(W + (size_t)(h0 + 16) * C2);
        const float4* r3 = (const float4*)(W + (size_t)(h0 + 24) * C2);
        float acc[4] = {0.f, 0.f, 0.f, 0.f};
        #pragma unroll 5
        for (int c4 = 0; c4 < 75; c4++) {
            float4 w0 = r0[c4], w1 = r1[c4], w2 = r2[c4], w3 = r3[c4];
            const float* gcol = &gmT[c4 * 4][0] + lane;
            float m0 = gcol[0], m1 = gcol[32], m2 = gcol[64], m3 = gcol[96];
            acc[0] += w0.x * m0 + w0.y * m1 + w0.z * m2 + w0.w * m3;
            acc[1] += w1.x * m0 + w1.y * m1 + w1.z * m2 + w1.w * m3;
            acc[2] += w2.x * m0 + w2.y * m1 + w2.z * m2 + w2.w * m3;
            acc[3] += w3.x * m0 + w3.y * m1 + w3.z * m2 + w3.w * m3;
        }
        #pragma unroll
        for (int hh = 0; hh < 4; hh++) {
            int h = h0 + hh * 8;
            if (h < C2) g_c1[(size_t)(bbase + lane) * C2 + h] = acc[hh];
        }
    } else {
        float* mvec = shm;
        int b = blk - 152;
        for (int c = tid; c < DF; c += 256)
            mvec[c] = g_meaning[b * DF + c];
        __syncthreads();

        const float* Wm = muWall + (size_t)p * DS * C2;
        for (int d = warp; d < DS; d += 8) {
            float acc = 0.f;
            const float* r = Wm + (size_t)d * C2 + DF;
            for (int c = lane; c < DF; c += 32) acc += r[c] * mvec[c];
            acc = warp_red(acc);
            if (lane == 0) g_cmu[b * DS + d] = acc;
        }
        if (warp == 0) {
            const float* gw = gWall + p * C2 + DF;
            float acc = 0.f;
            for (int c = lane; c < DF; c += 32) acc += gw[c] * mvec[c];
            acc = warp_red(acc);
            if (lane == 0) g_cgate[b] = acc;
        }
        if (warp == 1) {
            float s1 = 0.f, s2 = 0.f;
            for (int c = lane; c < DF; c += 32) { float v = mvec[c]; s1 += v; s2 += v * v; }
            s1 = warp_red(s1); s2 = warp_red(s2);
            if (lane == 0) { g_csum[b] = s1; g_csum2[b] = s2; }
        }
    }
}

// ---------------- K4: refinement — 16-k panels, round-9 sync skeleton ----------------
__global__ void __launch_bounds__(THR, 1) k_refine(int p,
    const float* __restrict__ mubAll,
    const float* __restrict__ gWall, const float* __restrict__ gbAll,
    const float* __restrict__ b2All)
{
    extern __shared__ float sm[];
    float* sX   = sm + OFF_X;
    float* sC1  = sm + OFF_SC1;
    float* sU1  = sm + OFF_SU1;
    float* sV1  = sm + OFF_SV1;
    float* sBmu = sm + OFF_SBMU;
    float* sB2  = sm + OFF_SB2;
    float* sA   = sm + OFF_SA;
    float* sM2  = sm + OFF_SM2;
    const uint32_t* sXu = (const uint32_t*)sX;

    int b   = blockIdx.y;
    int s0  = blockIdx.x * T_TOK;
    int tid = threadIdx.x;
    int tokBase = b * SS + s0;
    int w = tid >> 5, lane = tid & 31;
    int kq = lane & 3, rq = lane >> 2;

    uint32_t smem_u32 = (uint32_t)__cvta_generic_to_shared(sm);
    uint32_t w1_u32[2] = { smem_u32 + OFF_W1A * 4, smem_u32 + OFF_W1B * 4 };
    uint32_t w2_u32[2] = { smem_u32 + OFF_SW2 * 4, smem_u32 + (OFF_SW2 + PAN2) * 4 };
    uint32_t mb = smem_u32 + OFF_MBAR * 4;

    if (tid == 0) {
        #pragma unroll
        for (int i = 0; i < 4; i++) MBAR_INIT(mb + 8 * i, 1);
        asm volatile("fence.proxy.async.shared::cta;" ::: "memory");
    }
    __syncthreads();

    // prologue: panel 0 of GEMM1 into aliased region (rows 304+, disjoint from B1)
    if (tid == 0) {
        MBAR_EXPECT_TX(mb, SZP1);
        BULK_CP(w1_u32[0], g_W1f, SZP1, mb);
    }

    for (int i = tid; i < C2; i += THR) {
        sC1[i] = g_c1[b * C2 + i];
        sU1[i] = g_u1[i];
        sV1[i] = g_v1[i];
    }
    if (tid < DS)  sBmu[tid] = mubAll[p * DS + tid] + g_cmu[b * DS + tid];
    if (tid >= THR - DF) sB2[tid - (THR - DF)] = b2All[p * DF + (tid - (THR - DF))];

    for (int idx = tid; idx < DF * T_TOK; idx += THR) {
        int t = idx / DF;
        int f = idx - t * DF;
        sX[f * LDB1 + t] = tf32r(g_feat[(size_t)(tokBase + t) * DF + f]);
    }
    for (int idx = tid; idx < 4 * LDB1; idx += THR) sX[DF * LDB1 + idx] = 0.f;
    __syncthreads();

    // ---- per-token LN stats + alpha gate ----
    {
        float csum = g_csum[b], csum2 = g_csum2[b], cgate = g_cgate[b];
        const float* gw = gWall + p * C2;
        float gbv = gbAll[p];
        #pragma unroll
        for (int tt = 0; tt < 4; tt++) {
            int t = w * 4 + tt;
            float s1 = 0.f, s2 = 0.f, gd = 0.f;
            for (int k = lane; k < DF; k += 32) {
                float v = sX[k * LDB1 + t];
                s1 += v; s2 += v * v; gd += gw[k] * v;
            }
            s1 = warp_red(s1); s2 = warp_red(s2); gd = warp_red(gd);
            if (lane == 0) {
                float mean = (s1 + csum) * (1.0f / C2);
                float var  = (s2 + csum2) * (1.0f / C2) - mean * mean;
                float rstd = rsqrtf(var + 1e-5f);
                sA[t]  = rstd;
                sM2[t] = -mean * rstd;
                g_alpha[tokBase + t] *= sigmoidf_(gd + cgate + gbv);
            }
        }
    }

    // ================= GEMM1: [672 x 304] @ [304 x 64], 19 x 16-k panels =================
    float acc[3][32];
    #pragma unroll
    for (int i = 0; i < 3; i++)
        #pragma unroll
        for (int j = 0; j < 32; j++) acc[i][j] = 0.f;

    for (int s = 0; s < NP1; s++) {
        __syncthreads();   // all warps done with buf (s+1)&1 (iter s-1)
        if (tid == 0 && s + 1 < NP1) {
            uint32_t m = mb + 8 * ((s + 1) & 1);
            MBAR_EXPECT_TX(m, SZP1);
            BULK_CP(w1_u32[(s + 1) & 1], g_W1f + (size_t)(s + 1) * PAN1, SZP1, m);
        }
        mbar_wait(mb + 8 * (s & 1), (s >> 1) & 1);

        const float* swp = sm + ((s & 1) ? OFF_W1B : OFF_W1A);
        #pragma unroll
        for (int sub = 0; sub < 2; sub++) {
            const float* swb = swp + sub * (NT1 * 128);
            int k0 = s * 16 + sub * 8;
            #pragma unroll
            for (int hb = 0; hb < 2; hb++) {
                uint32_t bb0[4], bb1[4];
                #pragma unroll
                for (int nl = 0; nl < 4; nl++) {
                    int n = (hb * 4 + nl) * 8 + rq;
                    bb0[nl] = sXu[(k0 + kq)     * LDB1 + n];
                    bb1[nl] = sXu[(k0 + kq + 4) * LDB1 + n];
                }
                #pragma unroll
                for (int i = 0; i < 3; i++) {
                    int tile = w + NWARP * i;
                    if (tile < NT1) {
                        uint4 aa = *(const uint4*)(swb + tile * 128 + lane * 4);
                        #pragma unroll
                        for (int nl = 0; nl < 4; nl++)
                            mma_tf32(&acc[i][hb * 16 + nl * 4], aa, bb0[nl], bb1[nl]);
                    }
                }
            }
        }
    }
    __syncthreads();   // all GEMM1 reads (B rows + aliased weight rows) done

    // prefetch GEMM2 panel 0 into static SW2 (overlaps epilogue)
    if (tid == 0) {
        MBAR_EXPECT_TX(mb + 16, SZP2);
        BULK_CP(w2_u32[0], g_W2f, SZP2, mb + 16);
    }

    // ---- GEMM1 epilogue: LN/GELU -> sH rows 0..599 ; mu rows -> tanh -> g_mu ----
    #pragma unroll
    for (int i = 0; i < 3; i++) {
        int tile = w + NWARP * i;
        if (tile < NT1) {
            int m0 = tile * 16;
            #pragma unroll
            for (int half = 0; half < 2; half++) {
                int r = m0 + rq + half * 8;
                if (r < C2) {
                    float c1v = sC1[r], u1v = sU1[r], v1v = sV1[r];
                    #pragma unroll
                    for (int hb = 0; hb < 2; hb++)
                        #pragma unroll
                        for (int nl = 0; nl < 4; nl++)
                            #pragma unroll
                            for (int q = 0; q < 2; q++) {
                                int n = (hb * 4 + nl) * 8 + 2 * kq + q;
                                float a = acc[i][hb * 16 + nl * 4 + half * 2 + q];
                                float x = sA[n] * (a + c1v) + sM2[n] * u1v + v1v;
                                float gl = 0.5f * x * (1.0f + erff(x * 0.70710678118654752f));
                                sX[r * LDB1 + n] = tf32r(gl);
                            }
                } else if (r < C2 + DS) {
                    int d = r - C2;
                    float bm = sBmu[d];
                    #pragma unroll
                    for (int hb = 0; hb < 2; hb++)
                        #pragma unroll
                        for (int nl = 0; nl < 4; nl++)
                            #pragma unroll
                            for (int q = 0; q < 2; q++) {
                                int n = (hb * 4 + nl) * 8 + 2 * kq + q;
                                float a = acc[i][hb * 16 + nl * 4 + half * 2 + q];
                                g_mu[(size_t)(tokBase + n) * DS + d] += tanhf(a + bm);
                            }
                }
            }
        }
    }
    // zero sH K-pad rows 600..607 (B side of the padded GEMM2 panel)
    for (int idx = tid; idx < 8 * LDB1; idx += THR) sX[C2 * LDB1 + idx] = 0.f;
    __syncthreads();   // sH (incl. pad rows) fully written before GEMM2 reads

    // ================= GEMM2: [304 x 608] @ [608 x 64], 38 x 16-k panels =================
    float ac2[2][32];
    #pragma unroll
    for (int i = 0; i < 2; i++)
        #pragma unroll
        for (int j = 0; j < 32; j++) ac2[i][j] = 0.f;

    for (int s = 0; s < NP2; s++) {
        __syncthreads();
        if (tid == 0 && s + 1 < NP2) {
            uint32_t m = mb + 16 + 8 * ((s + 1) & 1);
            MBAR_EXPECT_TX(m, SZP2);
            BULK_CP(w2_u32[(s + 1) & 1], g_W2f + (size_t)(s + 1) * PAN2, SZP2, m);
        }
        mbar_wait(mb + 16 + 8 * (s & 1), (s >> 1) & 1);

        const float* swp = sm + OFF_SW2 + (s & 1) * PAN2;
        #pragma unroll
        for (int sub = 0; sub < 2; sub++) {
            const float* swb = swp + sub * (NT2 * 128);
            int k0 = s * 16 + sub * 8;
            #pragma unroll
            for (int hb = 0; hb < 2; hb++) {
                uint32_t bb0[4], bb1[4];
                #pragma unroll
                for (int nl = 0; nl < 4; nl++) {
                    int n = (hb * 4 + nl) * 8 + rq;
                    bb0[nl] = sXu[(k0 + kq)     * LDB1 + n];
                    bb1[nl] = sXu[(k0 + kq + 4) * LDB1 + n];
                }
                #pragma unroll
                for (int i = 0; i < 2; i++) {
                    int tile = w + NWARP * i;
                    if (tile < NT2) {
                        uint4 aa = *(const uint4*)(swb + tile * 128 + lane * 4);
                        #pragma unroll
                        for (int nl = 0; nl < 4; nl++)
                            mma_tf32(&ac2[i][hb * 16 + nl * 4], aa, bb0[nl], bb1[nl]);
                    }
                }
            }
        }
    }
    __syncthreads();

    // ---- stage dfeat into sX (sH dead) ----
    #pragma unroll
    for (int i = 0; i < 2; i++) {
        int tile = w + NWARP * i;
        if (tile < NT2) {
            int m0 = tile * 16;
            #pragma unroll
            for (int half = 0; half < 2; half++) {
                int f = m0 + rq + half * 8;
                if (f < DF) {
                    #pragma unroll
                    for (int hb = 0; hb < 2; hb++)
                        #pragma unroll
                        for (int nl = 0; nl < 4; nl++)
                            #pragma unroll
                            for (int q = 0; q < 2; q++) {
                                int n = (hb * 4 + nl) * 8 + 2 * kq + q;
                                sX[f * LDB1 + n] = ac2[i][hb * 16 + nl * 4 + half * 2 + q];
                            }
                }
            }
        }
    }
    __syncthreads();

    // ---- coalesced residual writeback ----
    for (int idx = tid; idx < DF * T_TOK; idx += THR) {
        int t = idx / DF;
        int f = idx - t * DF;
        size_t a = (size_t)(tokBase + t) * DF + f;
        g_feat[a] = g_feat[a] + sX[f * LDB1 + t] + sB2[f];
    }
}

// ---------------- host launch ----------------
extern "C" void kernel_launch(void* const* d_in, const int* in_sizes, int n_in,
                              void* d_out, int out_size)
{
    const int*   ids     = (const int*)  d_in[0];
    const float* mu_t    = (const float*)d_in[2];
    const float* lv_t    = (const float*)d_in[3];
    const float* a_t     = (const float*)d_in[4];
    const float* f_t     = (const float*)d_in[5];
    const float* log_tau = (const float*)d_in[6];
    const float* pos_mu  = (const float*)d_in[7];
    const float* pos_a   = (const float*)d_in[8];
    const float* muW     = (const float*)d_in[9];
    const float* mub     = (const float*)d_in[10];
    const float* gW      = (const float*)d_in[11];
    const float* gb      = (const float*)d_in[12];
    const float* lng     = (const float*)d_in[13];
    const float* lnb     = (const float*)d_in[14];
    const float* W1      = (const float*)d_in[15];
    const float* b1      = (const float*)d_in[16];
    const float* W2      = (const float*)d_in[17];
    const float* b2      = (const float*)d_in[18];
    float* out = (float*)d_out;

    cudaFuncSetAttribute(k_refine, cudaFuncAttributeMaxDynamicSharedMemorySize, SMEM_BYTES);

    dim3 grid(SS / T_TOK, BB);
    for (int p = 0; p < NPASS - 1; p++) {
        int init_blocks = (p == 0) ? NTOK : 0;
        k_init_prep<<<init_blocks + NPREP + C2, 128>>>(init_blocks, p,
            ids, mu_t, lv_t, a_t, f_t, pos_mu, pos_a, W1, lng, lnb, b1, muW, W2);
        k_render<<<BB, 512>>>(log_tau, out, 0);
        k_ctx<<<408, 256>>>(p, W1, lng, muW, gW);
        k_refine<<<grid, THR, SMEM_BYTES>>>(p, mub, gW, gb, b2);
    }
    k_render<<<BB, 512>>>(log_tau, out, 1);
}

// round 14
// speedup vs baseline: 1.4773x; 1.0848x over previous
#include <cuda_runtime.h>
#include <cuda_bf16.h>
#include <math.h>
#include <stdint.h>

// ---------------- problem constants ----------------
#define BB    256
#define SS    512
#define DS    64
#define DF    300
#define C2    600
#define NPASS 4
#define NTOK  (BB*SS)

// ---------------- refine tiling (tf32 mma.sync m16n8k8) ----------------
#define T_TOK 64
#define THR   512
#define NWARP 16
#define NT1   42
#define NS1   38            // 8-k steps, GEMM1 (K=304)
#define NT2   19
#define NS2P  76            // 8-k steps, GEMM2 (K padded 600->608)
#define NP1   19            // 16-k panels GEMM1
#define NP2   38            // 16-k panels GEMM2
#define LDB1  72            // stride for dfeat staging only
#define PAN1  (2*NT1*128)   // 10752 floats / panel
#define PAN2  (2*NT2*128)   // 4864 floats / panel
#define SZP1  (PAN1*4)
#define SZP2  (PAN2*4)
#define NPREP (NS1*NT1 + NS2P*NT2)   // 3040

// smem float offsets. X region (43776 floats):
//   GEMM1 phase: B1 fragments ksteps 0..37 -> floats [0, 19456); W1 panel
//     double-buffer aliased at [21888, 43392).
//   GEMM2 phase: sH fragments ksteps 0..75 -> floats [0, 38912).
//   final: dfeat staged [f*LDB1+n], floats [0, 21600).
#define XROWS    608
#define OFF_X    0
#define OFF_W1A  (304*LDB1)          // 21888
#define OFF_W1B  (OFF_W1A + PAN1)    // 32640 (ends 43392 <= 43776)
#define OFF_SW2  (XROWS*LDB1)        // 43776
#define OFF_SC1  (OFF_SW2 + 2*PAN2)
#define OFF_SU1  (OFF_SC1 + C2)
#define OFF_SV1  (OFF_SU1 + C2)
#define OFF_SBMU (OFF_SV1 + C2)
#define OFF_SB2  (OFF_SBMU + DS)
#define OFF_SA   (OFF_SB2 + DF)
#define OFF_SM2  (OFF_SA  + T_TOK)
#define OFF_MBAR (OFF_SM2 + T_TOK)
#define SMEM_FLOATS (OFF_MBAR + 8)
#define SMEM_BYTES  (SMEM_FLOATS * 4)

// ---------------- persistent scratch ----------------
__device__ float g_mu   [NTOK * DS];
__device__ float g_ivar [NTOK * DS];
__device__ float g_alpha[NTOK];
__device__ float g_feat [NTOK * DF];
__device__ float g_w    [NTOK];
__device__ float g_winv [BB];
__device__ float g_meaning[BB * DF];
__device__ float g_c1  [BB * C2];
__device__ float g_cmu [BB * DS];
__device__ float g_cgate[BB];
__device__ float g_csum [BB];
__device__ float g_csum2[BB];
__device__ float g_u1  [C2];
__device__ float g_v1  [C2];
__device__ __align__(16) float g_W1f[NS1 * NT1 * 128];
__device__ __align__(16) float g_W2f[NS2P * NT2 * 128];

__device__ __forceinline__ float sigmoidf_(float x) { return 1.0f / (1.0f + expf(-x)); }
__device__ __forceinline__ float warp_red(float x) {
    #pragma unroll
    for (int o = 16; o; o >>= 1) x += __shfl_xor_sync(0xffffffffu, x, o);
    return x;
}
__device__ __forceinline__ float tf32r(float x) {
    uint32_t u;
    asm("cvt.rna.tf32.f32 %0, %1;" : "=r"(u) : "f"(x));
    return __uint_as_float(u);
}
__device__ __forceinline__ void mma_tf32(float* d, uint4 a, uint32_t b0, uint32_t b1) {
    asm volatile(
        "mma.sync.aligned.m16n8k8.row.col.f32.tf32.tf32.f32 "
        "{%0,%1,%2,%3}, {%4,%5,%6,%7}, {%8,%9}, {%0,%1,%2,%3};"
        : "+f"(d[0]), "+f"(d[1]), "+f"(d[2]), "+f"(d[3])
        : "r"(a.x), "r"(a.y), "r"(a.z), "r"(a.w), "r"(b0), "r"(b1));
}
// B-fragment address: value (k, n) for mma.m16n8k8 thread layout, packed so each
// lane's 16 values per 8-k step are 4 uint4s at (lane + j*32) within a 512-float block.
__device__ __forceinline__ int frag_addr(int k, int n) {
    return ((k >> 3) << 9)
         + ((((n >> 4) << 5) + ((n & 7) << 2) + (k & 3)) << 2)
         + (((n >> 3) & 1) << 1) + ((k >> 2) & 1);
}
#define MBAR_INIT(mbar_u32, cnt) \
    asm volatile("mbarrier.init.shared.b64 [%0], %1;" :: "r"(mbar_u32), "r"(cnt) : "memory")
#define MBAR_EXPECT_TX(mbar_u32, bytes) \
    asm volatile("mbarrier.arrive.expect_tx.shared.b64 _, [%0], %1;" :: "r"(mbar_u32), "r"(bytes) : "memory")
#define BULK_CP(dst_u32, src_ptr, nbytes, mbar_u32) \
    asm volatile("cp.async.bulk.shared::cluster.global.mbarrier::complete_tx::bytes [%0], [%1], %2, [%3];" \
        :: "r"(dst_u32), "l"(src_ptr), "r"(nbytes), "r"(mbar_u32) : "memory")
__device__ __forceinline__ void mbar_wait(uint32_t mbar, uint32_t parity) {
    asm volatile(
        "{\n\t.reg .pred P;\n\t"
        "WL%=:\n\t"
        "mbarrier.try_wait.parity.acquire.cta.shared::cta.b64 P, [%0], %1, 0x989680;\n\t"
        "@P bra WD%=;\n\t"
        "bra WL%=;\n\t"
        "WD%=:\n\t}"
        :: "r"(mbar), "r"(parity) : "memory");
}

// ---------------- K1: token init + weight-fragment prep + u1/v1 (grid-split) ----------------
__global__ void __launch_bounds__(128) k_init_prep(int init_blocks, int p,
                       const int* __restrict__ ids,
                       const float* __restrict__ mu_t,
                       const float* __restrict__ lv_t,
                       const float* __restrict__ a_t,
                       const float* __restrict__ f_t,
                       const float* __restrict__ pos_mu,
                       const float* __restrict__ pos_alpha,
                       const float* __restrict__ W1all,
                       const float* __restrict__ lng,
                       const float* __restrict__ lnb,
                       const float* __restrict__ b1,
                       const float* __restrict__ muWall,
                       const float* __restrict__ W2all)
{
    __shared__ float pu[4], pv[4];
    int blk = blockIdx.x;
    int tid = threadIdx.x;

    if (blk < init_blocks) {
        int i = blk;
        int s = i & (SS - 1);
        int id = ids[i];
        if (tid < 64) {
            g_mu  [i * DS + tid] = mu_t[id * DS + tid] + pos_mu[s * DS + tid];
            g_ivar[i * DS + tid] = expf(-lv_t[id * DS + tid]);
        }
        for (int f = tid; f < DF; f += 128)
            g_feat[i * DF + f] = f_t[id * DF + f];
        if (tid == 0)
            g_alpha[i] = sigmoidf_(a_t[id]) * sigmoidf_(pos_alpha[s]);
        return;
    }
    int pb = blk - init_blocks;
    if (pb < NPREP) {
        int lane = tid >> 2, v = tid & 3;
        int rq = lane >> 2, kq = lane & 3;
        if (pb < NS1 * NT1) {
            int s = pb / NT1, t = pb - s * NT1;
            int r = t * 16 + rq + (v & 1) * 8;
            int k = s * 8 + kq + (v >> 1) * 4;
            float val = 0.f;
            if (k < DF) {
                if (r < C2)
                    val = W1all[(size_t)p * C2 * C2 + (size_t)r * C2 + k] * lng[p * C2 + k];
                else if (r < C2 + DS)
                    val = muWall[(size_t)p * DS * C2 + (size_t)(r - C2) * C2 + k];
            }
            g_W1f[(size_t)pb * 128 + tid] = tf32r(val);
        } else {
            int b2 = pb - NS1 * NT1;
            int s = b2 / NT2, t = b2 - s * NT2;
            int r = t * 16 + rq + (v & 1) * 8;
            int k = s * 8 + kq + (v >> 1) * 4;
            float val = 0.f;
            if (r < DF && k < C2)
                val = W2all[(size_t)p * DF * C2 + (size_t)r * C2 + k];
            g_W2f[(size_t)b2 * 128 + tid] = tf32r(val);
        }
        return;
    }
    {
        int h = pb - NPREP;
        const float* row = W1all + (size_t)p * C2 * C2 + (size_t)h * C2;
        const float* g   = lng + p * C2;
        const float* bb  = lnb + p * C2;
        float u = 0.f, v = 0.f;
        for (int c = tid; c < C2; c += 128) {
            float w = row[c];
            u += w * g[c];
            v += w * bb[c];
        }
        u = warp_red(u); v = warp_red(v);
        int warp = tid >> 5, lane = tid & 31;
        if (lane == 0) { pu[warp] = u; pv[warp] = v; }
        __syncthreads();
        if (tid == 0) {
            g_u1[h] = pu[0] + pu[1] + pu[2] + pu[3];
            g_v1[h] = pv[0] + pv[1] + pv[2] + pv[3] + b1[p * C2 + h];
        }
    }
}

// ---------------- K2: merged render — centroid + weights + meaning (per-b) ----------------
__global__ void __launch_bounds__(512) k_render(const float* __restrict__ log_tau,
                                                float* __restrict__ out_final,
                                                int write_final)
{
    __shared__ __align__(16) float cent[DS];
    __shared__ float part[8][DS];
    __shared__ float wv[SS];
    __shared__ float red[16];
    __shared__ float s_inv;
    __shared__ float pm[2][DF];

    int b = blockIdx.x, tid = threadIdx.x, base = b * SS;
    int warp = tid >> 5, lane = tid & 31;

    {
        int d = tid & 63, gq = tid >> 6;
        const float* mp = g_mu + (size_t)(base + gq * 64) * DS + d;
        float a0 = 0.f, a1 = 0.f;
        #pragma unroll 8
        for (int i = 0; i < 32; i++) {
            a0 += mp[i * DS];
            a1 += mp[(i + 32) * DS];
        }
        part[gq][d] = a0 + a1;
    }
    __syncthreads();
    if (tid < DS) {
        float c = 0.f;
        #pragma unroll
        for (int i = 0; i < 8; i++) c += part[i][tid];
        cent[tid] = c * (1.0f / SS);
    }
    __syncthreads();

    float nh_invtau = -0.5f / expf(log_tau[0]);
    {
        int s = tid;
        const float4* mu4 = (const float4*)(g_mu   + (size_t)(base + s) * DS);
        const float4* iv4 = (const float4*)(g_ivar + (size_t)(base + s) * DS);
        const float4* c4  = (const float4*)cent;
        float d2 = 0.f;
        #pragma unroll
        for (int q = 0; q < 16; q++) {
            float4 m = mu4[q], v = iv4[q], c = c4[q];
            float dx = c.x - m.x; d2 += dx * dx * v.x;
            float dy = c.y - m.y; d2 += dy * dy * v.y;
            float dz = c.z - m.z; d2 += dz * dz * v.z;
            float dw = c.w - m.w; d2 += dw * dw * v.w;
        }
        float w = g_alpha[base + s] * expf(nh_invtau * d2);
        wv[s] = w;
        float t = warp_red(w);
        if (lane == 0) red[warp] = t;
    }
    __syncthreads();
    if (tid == 0) {
        float x = 0.f;
        #pragma unroll
        for (int i = 0; i < 16; i++) x += red[i];
        s_inv = 1.0f / (x + 1e-8f);
    }
    __syncthreads();

    {
        int g = tid >> 8, t = tid & 255;
        if (t < 150) {
            const float2* f2 = (const float2*)(g_feat + (size_t)base * DF) + t
                               + (size_t)(g * 256) * 150;
            const float* wp = wv + g * 256;
            float a0 = 0.f, a1 = 0.f;
            #pragma unroll 8
            for (int s = 0; s < 256; s++) {
                float2 v = f2[(size_t)s * 150];
                float ww = wp[s];
                a0 += ww * v.x; a1 += ww * v.y;
            }
            pm[g][2 * t]     = a0;
            pm[g][2 * t + 1] = a1;
        }
    }
    __syncthreads();
    if (tid < DF) {
        float* dst = write_final ? out_final : g_meaning;
        dst[b * DF + tid] = (pm[0][tid] + pm[1][tid]) * s_inv;
    }
}

// ---------------- K3: context — tiled c1 GEMM + per-b cmu/gate/sums ----------------
__global__ void __launch_bounds__(256) k_ctx(int p,
                                             const float* __restrict__ W1all,
                                             const float* __restrict__ lng,
                                             const float* __restrict__ muWall,
                                             const float* __restrict__ gWall)
{
    __shared__ float shm[300 * 32];
    int blk = blockIdx.x;
    int tid = threadIdx.x;
    int warp = tid >> 5, lane = tid & 31;

    if (blk < 152) {
        float (*gmT)[32] = (float (*)[32])shm;
        int hbase = (blk >> 3) * 32;
        int bbase = (blk & 7) * 32;
        const float* g = lng + p * C2 + DF;
        for (int idx = tid; idx < 300 * 32; idx += 256) {
            int c = idx >> 5, bc = idx & 31;
            gmT[c][bc] = g[c] * g_meaning[(size_t)(bbase + bc) * DF + c];
        }
        __syncthreads();

        int h0 = hbase + warp;
        const float* W = W1all + (size_t)p * C2 * C2 + DF;
        const float4* r0 = (const float4*)(W + (size_t)(h0)      * C2);
        const float4* r1 = (const float4*)(W + (size_t)(h0 + 8)  * C2);
        const float4* r2 = (const float4*)(W + (size_t)(h0 + 16) * C2);
        const float4* r3 = (const float4*)(W + (size_t)(h0 + 24) * C2);
        float acc[4] = {0.f, 0.f, 0.f, 0.f};
        #pragma unroll 5
        for (int c4 = 0; c4 < 75; c4++) {
            float4 w0 = r0[c4], w1 = r1[c4], w2 = r2[c4], w3 = r3[c4];
            const float* gcol = &gmT[c4 * 4][0] + lane;
            float m0 = gcol[0], m1 = gcol[32], m2 = gcol[64], m3 = gcol[96];
            acc[0] += w0.x * m0 + w0.y * m1 + w0.z * m2 + w0.w * m3;
            acc[1] += w1.x * m0 + w1.y * m1 + w1.z * m2 + w1.w * m3;
            acc[2] += w2.x * m0 + w2.y * m1 + w2.z * m2 + w2.w * m3;
            acc[3] += w3.x * m0 + w3.y * m1 + w3.z * m2 + w3.w * m3;
        }
        #pragma unroll
        for (int hh = 0; hh < 4; hh++) {
            int h = h0 + hh * 8;
            if (h < C2) g_c1[(size_t)(bbase + lane) * C2 + h] = acc[hh];
        }
    } else {
        float* mvec = shm;
        int b = blk - 152;
        for (int c = tid; c < DF; c += 256)
            mvec[c] = g_meaning[b * DF + c];
        __syncthreads();

        const float* Wm = muWall + (size_t)p * DS * C2;
        for (int d = warp; d < DS; d += 8) {
            float acc = 0.f;
            const float* r = Wm + (size_t)d * C2 + DF;
            for (int c = lane; c < DF; c += 32) acc += r[c] * mvec[c];
            acc = warp_red(acc);
            if (lane == 0) g_cmu[b * DS + d] = acc;
        }
        if (warp == 0) {
            const float* gw = gWall + p * C2 + DF;
            float acc = 0.f;
            for (int c = lane; c < DF; c += 32) acc += gw[c] * mvec[c];
            acc = warp_red(acc);
            if (lane == 0) g_cgate[b] = acc;
        }
        if (warp == 1) {
            float s1 = 0.f, s2 = 0.f;
            for (int c = lane; c < DF; c += 32) { float v = mvec[c]; s1 += v; s2 += v * v; }
            s1 = warp_red(s1); s2 = warp_red(s2);
            if (lane == 0) { g_csum[b] = s1; g_csum2[b] = s2; }
        }
    }
}

// ---------------- K4: refinement — fragment-ordered B, 16-k panels ----------------
__global__ void __launch_bounds__(THR, 1) k_refine(int p,
    const float* __restrict__ mubAll,
    const float* __restrict__ gWall, const float* __restrict__ gbAll,
    const float* __restrict__ b2All)
{
    extern __shared__ float sm[];
    float* sX   = sm + OFF_X;
    float* sC1  = sm + OFF_SC1;
    float* sU1  = sm + OFF_SU1;
    float* sV1  = sm + OFF_SV1;
    float* sBmu = sm + OFF_SBMU;
    float* sB2  = sm + OFF_SB2;
    float* sA   = sm + OFF_SA;
    float* sM2  = sm + OFF_SM2;

    int b   = blockIdx.y;
    int s0  = blockIdx.x * T_TOK;
    int tid = threadIdx.x;
    int tokBase = b * SS + s0;
    int w = tid >> 5, lane = tid & 31;
    int kq = lane & 3, rq = lane >> 2;

    uint32_t smem_u32 = (uint32_t)__cvta_generic_to_shared(sm);
    uint32_t w1_u32[2] = { smem_u32 + OFF_W1A * 4, smem_u32 + OFF_W1B * 4 };
    uint32_t w2_u32[2] = { smem_u32 + OFF_SW2 * 4, smem_u32 + (OFF_SW2 + PAN2) * 4 };
    uint32_t mb = smem_u32 + OFF_MBAR * 4;

    if (tid == 0) {
        #pragma unroll
        for (int i = 0; i < 4; i++) MBAR_INIT(mb + 8 * i, 1);
        asm volatile("fence.proxy.async.shared::cta;" ::: "memory");
    }
    __syncthreads();

    if (tid == 0) {
        MBAR_EXPECT_TX(mb, SZP1);
        BULK_CP(w1_u32[0], g_W1f, SZP1, mb);
    }

    for (int i = tid; i < C2; i += THR) {
        sC1[i] = g_c1[b * C2 + i];
        sU1[i] = g_u1[i];
        sV1[i] = g_v1[i];
    }
    if (tid < DS)  sBmu[tid] = mubAll[p * DS + tid] + g_cmu[b * DS + tid];
    if (tid >= THR - DF) sB2[tid - (THR - DF)] = b2All[p * DF + (tid - (THR - DF))];

    // ---- load features (tf32) into fragment-ordered B1 ----
    for (int idx = tid; idx < DF * T_TOK; idx += THR) {
        int t = idx / DF;
        int f = idx - t * DF;
        sX[frag_addr(f, t)] = tf32r(g_feat[(size_t)(tokBase + t) * DF + f]);
    }
    // zero K-pad sub-elements of kstep 37 (f = 300..303 positions: odd e)
    if (tid < 256)
        sX[37 * 512 + (tid >> 1) * 4 + ((tid & 1) << 1) + 1] = 0.f;
    __syncthreads();

    // ---- per-token LN stats + alpha gate (reads via frag layout) ----
    {
        float csum = g_csum[b], csum2 = g_csum2[b], cgate = g_cgate[b];
        const float* gw = gWall + p * C2;
        float gbv = gbAll[p];
        #pragma unroll
        for (int tt = 0; tt < 4; tt++) {
            int t = w * 4 + tt;
            float s1 = 0.f, s2 = 0.f, gd = 0.f;
            for (int k = lane; k < DF; k += 32) {
                float v = sX[frag_addr(k, t)];
                s1 += v; s2 += v * v; gd += gw[k] * v;
            }
            s1 = warp_red(s1); s2 = warp_red(s2); gd = warp_red(gd);
            if (lane == 0) {
                float mean = (s1 + csum) * (1.0f / C2);
                float var  = (s2 + csum2) * (1.0f / C2) - mean * mean;
                float rstd = rsqrtf(var + 1e-5f);
                sA[t]  = rstd;
                sM2[t] = -mean * rstd;
                g_alpha[tokBase + t] *= sigmoidf_(gd + cgate + gbv);
            }
        }
    }

    // ================= GEMM1: [672 x 304] @ [304 x 64], 19 x 16-k panels =================
    float acc[3][32];
    #pragma unroll
    for (int i = 0; i < 3; i++)
        #pragma unroll
        for (int j = 0; j < 32; j++) acc[i][j] = 0.f;

    for (int s = 0; s < NP1; s++) {
        __syncthreads();
        if (tid == 0 && s + 1 < NP1) {
            uint32_t m = mb + 8 * ((s + 1) & 1);
            MBAR_EXPECT_TX(m, SZP1);
            BULK_CP(w1_u32[(s + 1) & 1], g_W1f + (size_t)(s + 1) * PAN1, SZP1, m);
        }
        mbar_wait(mb + 8 * (s & 1), (s >> 1) & 1);

        const float* swp = sm + ((s & 1) ? OFF_W1B : OFF_W1A);
        #pragma unroll
        for (int sub = 0; sub < 2; sub++) {
            const float* swb = swp + sub * (NT1 * 128);
            const uint4* bp = (const uint4*)(sX + (s * 2 + sub) * 512) + lane;
            uint4 u0 = bp[0], u1 = bp[32], u2 = bp[64], u3 = bp[96];
            #pragma unroll
            for (int i = 0; i < 3; i++) {
                int tile = w + NWARP * i;
                if (tile < NT1) {
                    uint4 aa = *(const uint4*)(swb + tile * 128 + lane * 4);
                    mma_tf32(&acc[i][0],  aa, u0.x, u0.y);
                    mma_tf32(&acc[i][4],  aa, u0.z, u0.w);
                    mma_tf32(&acc[i][8],  aa, u1.x, u1.y);
                    mma_tf32(&acc[i][12], aa, u1.z, u1.w);
                    mma_tf32(&acc[i][16], aa, u2.x, u2.y);
                    mma_tf32(&acc[i][20], aa, u2.z, u2.w);
                    mma_tf32(&acc[i][24], aa, u3.x, u3.y);
                    mma_tf32(&acc[i][28], aa, u3.z, u3.w);
                }
            }
        }
    }
    __syncthreads();   // all GEMM1 reads done before epilogue rewrites sX

    // prefetch GEMM2 panel 0 (overlaps epilogue)
    if (tid == 0) {
        MBAR_EXPECT_TX(mb + 16, SZP2);
        BULK_CP(w2_u32[0], g_W2f, SZP2, mb + 16);
    }

    // ---- GEMM1 epilogue: LN/GELU -> sH fragments ; mu rows -> tanh -> g_mu ----
    #pragma unroll
    for (int i = 0; i < 3; i++) {
        int tile = w + NWARP * i;
        if (tile < NT1) {
            int m0 = tile * 16;
            #pragma unroll
            for (int half = 0; half < 2; half++) {
                int r = m0 + rq + half * 8;
                if (r < C2) {
                    float c1v = sC1[r], u1v = sU1[r], v1v = sV1[r];
                    #pragma unroll
                    for (int nb = 0; nb < 8; nb++)
                        #pragma unroll
                        for (int q = 0; q < 2; q++) {
                            int n = nb * 8 + 2 * kq + q;
                            float a = acc[i][nb * 4 + half * 2 + q];
                            float x = sA[n] * (a + c1v) + sM2[n] * u1v + v1v;
                            float gl = 0.5f * x * (1.0f + erff(x * 0.70710678118654752f));
                            sX[frag_addr(r, n)] = tf32r(gl);
                        }
                } else if (r < C2 + DS) {
                    int d = r - C2;
                    float bm = sBmu[d];
                    #pragma unroll
                    for (int nb = 0; nb < 8; nb++)
                        #pragma unroll
                        for (int q = 0; q < 2; q++) {
                            int n = nb * 8 + 2 * kq + q;
                            float a = acc[i][nb * 4 + half * 2 + q];
                            g_mu[(size_t)(tokBase + n) * DS + d] += tanhf(a + bm);
                        }
                }
            }
        }
    }
    // zero K-pad kstep 75 (rows 600..607) of sH fragments
    if (tid < 512) sX[75 * 512 + tid] = 0.f;
    __syncthreads();   // sH (incl. pad) fully written before GEMM2 reads

    // ================= GEMM2: [304 x 608] @ [608 x 64], 38 x 16-k panels =================
    float ac2[2][32];
    #pragma unroll
    for (int i = 0; i < 2; i++)
        #pragma unroll
        for (int j = 0; j < 32; j++) ac2[i][j] = 0.f;

    for (int s = 0; s < NP2; s++) {
        __syncthreads();
        if (tid == 0 && s + 1 < NP2) {
            uint32_t m = mb + 16 + 8 * ((s + 1) & 1);
            MBAR_EXPECT_TX(m, SZP2);
            BULK_CP(w2_u32[(s + 1) & 1], g_W2f + (size_t)(s + 1) * PAN2, SZP2, m);
        }
        mbar_wait(mb + 16 + 8 * (s & 1), (s >> 1) & 1);

        const float* swp = sm + OFF_SW2 + (s & 1) * PAN2;
        #pragma unroll
        for (int sub = 0; sub < 2; sub++) {
            const float* swb = swp + sub * (NT2 * 128);
            const uint4* bp = (const uint4*)(sX + (s * 2 + sub) * 512) + lane;
            uint4 u0 = bp[0], u1 = bp[32], u2 = bp[64], u3 = bp[96];
            #pragma unroll
            for (int i = 0; i < 2; i++) {
                int tile = w + NWARP * i;
                if (tile < NT2) {
                    uint4 aa = *(const uint4*)(swb + tile * 128 + lane * 4);
                    mma_tf32(&ac2[i][0],  aa, u0.x, u0.y);
                    mma_tf32(&ac2[i][4],  aa, u0.z, u0.w);
                    mma_tf32(&ac2[i][8],  aa, u1.x, u1.y);
                    mma_tf32(&ac2[i][12], aa, u1.z, u1.w);
                    mma_tf32(&ac2[i][16], aa, u2.x, u2.y);
                    mma_tf32(&ac2[i][20], aa, u2.z, u2.w);
                    mma_tf32(&ac2[i][24], aa, u3.x, u3.y);
                    mma_tf32(&ac2[i][28], aa, u3.z, u3.w);
                }
            }
        }
    }
    __syncthreads();

    // ---- stage dfeat into sX[f*LDB1+n] (sH dead) ----
    #pragma unroll
    for (int i = 0; i < 2; i++) {
        int tile = w + NWARP * i;
        if (tile < NT2) {
            int m0 = tile * 16;
            #pragma unroll
            for (int half = 0; half < 2; half++) {
                int f = m0 + rq + half * 8;
                if (f < DF) {
                    #pragma unroll
                    for (int nb = 0; nb < 8; nb++)
                        #pragma unroll
                        for (int q = 0; q < 2; q++) {
                            int n = nb * 8 + 2 * kq + q;
                            sX[f * LDB1 + n] = ac2[i][nb * 4 + half * 2 + q];
                        }
                }
            }
        }
    }
    __syncthreads();

    // ---- coalesced residual writeback ----
    for (int idx = tid; idx < DF * T_TOK; idx += THR) {
        int t = idx / DF;
        int f = idx - t * DF;
        size_t a = (size_t)(tokBase + t) * DF + f;
        g_feat[a] = g_feat[a] + sX[f * LDB1 + t] + sB2[f];
    }
}

// ---------------- host launch ----------------
extern "C" void kernel_launch(void* const* d_in, const int* in_sizes, int n_in,
                              void* d_out, int out_size)
{
    const int*   ids     = (const int*)  d_in[0];
    const float* mu_t    = (const float*)d_in[2];
    const float* lv_t    = (const float*)d_in[3];
    const float* a_t     = (const float*)d_in[4];
    const float* f_t     = (const float*)d_in[5];
    const float* log_tau = (const float*)d_in[6];
    const float* pos_mu  = (const float*)d_in[7];
    const float* pos_a   = (const float*)d_in[8];
    const float* muW     = (const float*)d_in[9];
    const float* mub     = (const float*)d_in[10];
    const float* gW      = (const float*)d_in[11];
    const float* gb      = (const float*)d_in[12];
    const float* lng     = (const float*)d_in[13];
    const float* lnb     = (const float*)d_in[14];
    const float* W1      = (const float*)d_in[15];
    const float* b1      = (const float*)d_in[16];
    const float* W2      = (const float*)d_in[17];
    const float* b2      = (const float*)d_in[18];
    float* out = (float*)d_out;

    cudaFuncSetAttribute(k_refine, cudaFuncAttributeMaxDynamicSharedMemorySize, SMEM_BYTES);

    dim3 grid(SS / T_TOK, BB);
    for (int p = 0; p < NPASS - 1; p++) {
        int init_blocks = (p == 0) ? NTOK : 0;
        k_init_prep<<<init_blocks + NPREP + C2, 128>>>(init_blocks, p,
            ids, mu_t, lv_t, a_t, f_t, pos_mu, pos_a, W1, lng, lnb, b1, muW, W2);
        k_render<<<BB, 512>>>(log_tau, out, 0);
        k_ctx<<<408, 256>>>(p, W1, lng, muW, gW);
        k_refine<<<grid, THR, SMEM_BYTES>>>(p, mub, gW, gb, b2);
    }
    k_render<<<BB, 512>>>(log_tau, out, 1);
}

// round 17
// speedup vs baseline: 1.5513x; 1.0501x over previous
#include <cuda_runtime.h>
#include <cuda_bf16.h>
#include <math.h>
#include <stdint.h>

// ---------------- problem constants ----------------
#define BB    256
#define SS    512
#define DS    64
#define DF    300
#define C2    600
#define NPASS 4
#define NTOK  (BB*SS)

// ---------------- refine tiling (tf32 mma.sync m16n8k8) ----------------
#define T_TOK 64
#define THR   512
#define NWARP 16
#define NT1   42
#define NS1   38            // 8-k steps, GEMM1 (K=304)
#define NT2   19
#define NS2P  76            // 8-k steps, GEMM2 (K padded 600->608)
#define NP1   19            // 16-k panels GEMM1
#define NP2   38            // 16-k panels GEMM2
#define LDB1  72            // stride for dfeat staging only
#define PAN1  (2*NT1*128)   // 10752 floats / panel
#define PAN2  (2*NT2*128)   // 4864 floats / panel
#define SZP1  (PAN1*4)
#define SZP2  (PAN2*4)
#define NPREP (NS1*NT1 + NS2P*NT2)   // 3040 per pass
#define W1SZ  (NS1*NT1*128)          // per-pass W1 fragment floats
#define W2SZ  (NS2P*NT2*128)

// smem float offsets (X region time-aliased: B1 frags -> sH frags -> dfeat)
#define XROWS    608
#define OFF_X    0
#define OFF_W1A  (304*LDB1)          // 21888
#define OFF_W1B  (OFF_W1A + PAN1)    // 32640
#define OFF_SW2  (XROWS*LDB1)        // 43776
#define OFF_SC1  (OFF_SW2 + 2*PAN2)
#define OFF_SU1  (OFF_SC1 + C2)
#define OFF_SV1  (OFF_SU1 + C2)
#define OFF_SBMU (OFF_SV1 + C2)
#define OFF_SB2  (OFF_SBMU + DS)
#define OFF_SA   (OFF_SB2 + DF)
#define OFF_SM2  (OFF_SA  + T_TOK)
#define OFF_MBAR (OFF_SM2 + T_TOK)
#define SMEM_FLOATS (OFF_MBAR + 8)
#define SMEM_BYTES  (SMEM_FLOATS * 4)

// ---------------- persistent scratch ----------------
__device__ float g_mu   [NTOK * DS];
__device__ float g_ivar [NTOK * DS];
__device__ float g_alpha[NTOK];
__device__ float g_feat [NTOK * DF];
__device__ float g_w    [NTOK];
__device__ float g_winv [BB];
__device__ float g_meaning[BB * DF];
__device__ float g_c1  [BB * C2];
__device__ float g_cmu [BB * DS];
__device__ float g_cgate[BB];
__device__ float g_csum [BB];
__device__ float g_csum2[BB];
__device__ float g_u1  [3 * C2];
__device__ float g_v1  [3 * C2];
// fragment-ordered tf32 weights for ALL 3 passes (prepped once)
__device__ __align__(16) float g_W1f[3 * W1SZ];
__device__ __align__(16) float g_W2f[3 * W2SZ];

__device__ __forceinline__ float sigmoidf_(float x) { return 1.0f / (1.0f + expf(-x)); }
__device__ __forceinline__ float warp_red(float x) {
    #pragma unroll
    for (int o = 16; o; o >>= 1) x += __shfl_xor_sync(0xffffffffu, x, o);
    return x;
}
__device__ __forceinline__ float tf32r(float x) {
    uint32_t u;
    asm("cvt.rna.tf32.f32 %0, %1;" : "=r"(u) : "f"(x));
    return __uint_as_float(u);
}
__device__ __forceinline__ void mma_tf32(float* d, uint4 a, uint32_t b0, uint32_t b1) {
    asm volatile(
        "mma.sync.aligned.m16n8k8.row.col.f32.tf32.tf32.f32 "
        "{%0,%1,%2,%3}, {%4,%5,%6,%7}, {%8,%9}, {%0,%1,%2,%3};"
        : "+f"(d[0]), "+f"(d[1]), "+f"(d[2]), "+f"(d[3])
        : "r"(a.x), "r"(a.y), "r"(a.z), "r"(a.w), "r"(b0), "r"(b1));
}
// B-fragment address: value (k, n), packed so each lane's 16 values per 8-k
// step are 4 uint4s at (lane + j*32) within a 512-float block.
__device__ __forceinline__ int frag_addr(int k, int n) {
    return ((k >> 3) << 9)
         + ((((n >> 4) << 5) + ((n & 7) << 2) + (k & 3)) << 2)
         + (((n >> 3) & 1) << 1) + ((k >> 2) & 1);
}
#define MBAR_INIT(mbar_u32, cnt) \
    asm volatile("mbarrier.init.shared.b64 [%0], %1;" :: "r"(mbar_u32), "r"(cnt) : "memory")
#define MBAR_EXPECT_TX(mbar_u32, bytes) \
    asm volatile("mbarrier.arrive.expect_tx.shared.b64 _, [%0], %1;" :: "r"(mbar_u32), "r"(bytes) : "memory")
#define BULK_CP(dst_u32, src_ptr, nbytes, mbar_u32) \
    asm volatile("cp.async.bulk.shared::cluster.global.mbarrier::complete_tx::bytes [%0], [%1], %2, [%3];" \
        :: "r"(dst_u32), "l"(src_ptr), "r"(nbytes), "r"(mbar_u32) : "memory")
__device__ __forceinline__ void mbar_wait(uint32_t mbar, uint32_t parity) {
    asm volatile(
        "{\n\t.reg .pred P;\n\t"
        "WL%=:\n\t"
        "mbarrier.try_wait.parity.acquire.cta.shared::cta.b64 P, [%0], %1, 0x989680;\n\t"
        "@P bra WD%=;\n\t"
        "bra WL%=;\n\t"
        "WD%=:\n\t}"
        :: "r"(mbar), "r"(parity) : "memory");
}

// ---------------- K1: token init + ALL-pass weight prep + u1/v1 (grid-split) ----------------
__global__ void __launch_bounds__(128) k_init_prep(
                       const int* __restrict__ ids,
                       const float* __restrict__ mu_t,
                       const float* __restrict__ lv_t,
                       const float* __restrict__ a_t,
                       const float* __restrict__ f_t,
                       const float* __restrict__ pos_mu,
                       const float* __restrict__ pos_alpha,
                       const float* __restrict__ W1all,
                       const float* __restrict__ lng,
                       const float* __restrict__ lnb,
                       const float* __restrict__ b1,
                       const float* __restrict__ muWall,
                       const float* __restrict__ W2all)
{
    __shared__ float pu[4], pv[4];
    int blk = blockIdx.x;
    int tid = threadIdx.x;

    if (blk < NTOK) {
        int i = blk;
        int s = i & (SS - 1);
        int id = ids[i];
        if (tid < 64) {
            g_mu  [i * DS + tid] = mu_t[id * DS + tid] + pos_mu[s * DS + tid];
            g_ivar[i * DS + tid] = expf(-lv_t[id * DS + tid]);
        }
        for (int f = tid; f < DF; f += 128)
            g_feat[i * DF + f] = f_t[id * DF + f];
        if (tid == 0)
            g_alpha[i] = sigmoidf_(a_t[id]) * sigmoidf_(pos_alpha[s]);
        return;
    }
    int pb = blk - NTOK;
    if (pb < 3 * NPREP) {
        int pp = pb / NPREP;
        int q  = pb - pp * NPREP;
        int lane = tid >> 2, v = tid & 3;
        int rq = lane >> 2, kq = lane & 3;
        if (q < NS1 * NT1) {
            int s = q / NT1, t = q - s * NT1;
            int r = t * 16 + rq + (v & 1) * 8;
            int k = s * 8 + kq + (v >> 1) * 4;
            float val = 0.f;
            if (k < DF) {
                if (r < C2)
                    val = W1all[(size_t)pp * C2 * C2 + (size_t)r * C2 + k] * lng[pp * C2 + k];
                else if (r < C2 + DS)
                    val = muWall[(size_t)pp * DS * C2 + (size_t)(r - C2) * C2 + k];
            }
            g_W1f[(size_t)pp * W1SZ + (size_t)q * 128 + tid] = tf32r(val);
        } else {
            int b2 = q - NS1 * NT1;
            int s = b2 / NT2, t = b2 - s * NT2;
            int r = t * 16 + rq + (v & 1) * 8;
            int k = s * 8 + kq + (v >> 1) * 4;
            float val = 0.f;
            if (r < DF && k < C2)
                val = W2all[(size_t)pp * DF * C2 + (size_t)r * C2 + k];
            g_W2f[(size_t)pp * W2SZ + (size_t)b2 * 128 + tid] = tf32r(val);
        }
        return;
    }
    {
        int r = pb - 3 * NPREP;       // 0 .. 3*C2-1
        int pp = r / C2;
        int h  = r - pp * C2;
        const float* row = W1all + (size_t)pp * C2 * C2 + (size_t)h * C2;
        const float* g   = lng + pp * C2;
        const float* bb  = lnb + pp * C2;
        float u = 0.f, v = 0.f;
        for (int c = tid; c < C2; c += 128) {
            float w = row[c];
            u += w * g[c];
            v += w * bb[c];
        }
        u = warp_red(u); v = warp_red(v);
        int warp = tid >> 5, lane = tid & 31;
        if (lane == 0) { pu[warp] = u; pv[warp] = v; }
        __syncthreads();
        if (tid == 0) {
            g_u1[pp * C2 + h] = pu[0] + pu[1] + pu[2] + pu[3];
            g_v1[pp * C2 + h] = pv[0] + pv[1] + pv[2] + pv[3] + b1[pp * C2 + h];
        }
    }
}

// ---------------- K2: merged render — centroid + weights + meaning (per-b) ----------------
__global__ void __launch_bounds__(512) k_render(const float* __restrict__ log_tau,
                                                float* __restrict__ out_final,
                                                int write_final)
{
    __shared__ __align__(16) float cent[DS];
    __shared__ float part[8][DS];
    __shared__ float wv[SS];
    __shared__ float red[16];
    __shared__ float s_inv;
    __shared__ float pm[2][DF];

    int b = blockIdx.x, tid = threadIdx.x, base = b * SS;
    int warp = tid >> 5, lane = tid & 31;

    {
        int d = tid & 63, gq = tid >> 6;
        const float* mp = g_mu + (size_t)(base + gq * 64) * DS + d;
        float a0 = 0.f, a1 = 0.f;
        #pragma unroll 8
        for (int i = 0; i < 32; i++) {
            a0 += mp[i * DS];
            a1 += mp[(i + 32) * DS];
        }
        part[gq][d] = a0 + a1;
    }
    __syncthreads();
    if (tid < DS) {
        float c = 0.f;
        #pragma unroll
        for (int i = 0; i < 8; i++) c += part[i][tid];
        cent[tid] = c * (1.0f / SS);
    }
    __syncthreads();

    float nh_invtau = -0.5f / expf(log_tau[0]);
    {
        int s = tid;
        const float4* mu4 = (const float4*)(g_mu   + (size_t)(base + s) * DS);
        const float4* iv4 = (const float4*)(g_ivar + (size_t)(base + s) * DS);
        const float4* c4  = (const float4*)cent;
        float d2 = 0.f;
        #pragma unroll
        for (int q = 0; q < 16; q++) {
            float4 m = mu4[q], v = iv4[q], c = c4[q];
            float dx = c.x - m.x; d2 += dx * dx * v.x;
            float dy = c.y - m.y; d2 += dy * dy * v.y;
            float dz = c.z - m.z; d2 += dz * dz * v.z;
            float dw = c.w - m.w; d2 += dw * dw * v.w;
        }
        float w = g_alpha[base + s] * expf(nh_invtau * d2);
        wv[s] = w;
        float t = warp_red(w);
        if (lane == 0) red[warp] = t;
    }
    __syncthreads();
    if (tid == 0) {
        float x = 0.f;
        #pragma unroll
        for (int i = 0; i < 16; i++) x += red[i];
        s_inv = 1.0f / (x + 1e-8f);
    }
    __syncthreads();

    {
        int g = tid >> 8, t = tid & 255;
        if (t < 150) {
            const float2* f2 = (const float2*)(g_feat + (size_t)base * DF) + t
                               + (size_t)(g * 256) * 150;
            const float* wp = wv + g * 256;
            float a0 = 0.f, a1 = 0.f;
            #pragma unroll 8
            for (int s = 0; s < 256; s++) {
                float2 v = f2[(size_t)s * 150];
                float ww = wp[s];
                a0 += ww * v.x; a1 += ww * v.y;
            }
            pm[g][2 * t]     = a0;
            pm[g][2 * t + 1] = a1;
        }
    }
    __syncthreads();
    if (tid < DF) {
        float* dst = write_final ? out_final : g_meaning;
        dst[b * DF + tid] = (pm[0][tid] + pm[1][tid]) * s_inv;
    }
}

// ---------------- K3: context — tiled c1 GEMM + per-b cmu/gate/sums ----------------
__global__ void __launch_bounds__(256) k_ctx(int p,
                                             const float* __restrict__ W1all,
                                             const float* __restrict__ lng,
                                             const float* __restrict__ muWall,
                                             const float* __restrict__ gWall)
{
    __shared__ float shm[300 * 32];
    int blk = blockIdx.x;
    int tid = threadIdx.x;
    int warp = tid >> 5, lane = tid & 31;

    if (blk < 152) {
        float (*gmT)[32] = (float (*)[32])shm;
        int hbase = (blk >> 3) * 32;
        int bbase = (blk & 7) * 32;
        const float* g = lng + p * C2 + DF;
        for (int idx = tid; idx < 300 * 32; idx += 256) {
            int c = idx >> 5, bc = idx & 31;
            gmT[c][bc] = g[c] * g_meaning[(size_t)(bbase + bc) * DF + c];
        }
        __syncthreads();

        int h0 = hbase + warp;
        const float* W = W1all + (size_t)p * C2 * C2 + DF;
        const float4* r0 = (const float4*)(W + (size_t)(h0)      * C2);
        const float4* r1 = (const float4*)(W + (size_t)(h0 + 8)  * C2);
        const float4* r2 = (const float4*)(W + (size_t)(h0 + 16) * C2);
        const float4* r3 = (const float4*)(W + (size_t)(h0 + 24) * C2);
        float acc[4] = {0.f, 0.f, 0.f, 0.f};
        #pragma unroll 5
        for (int c4 = 0; c4 < 75; c4++) {
            float4 w0 = r0[c4], w1 = r1[c4], w2 = r2[c4], w3 = r3[c4];
            const float* gcol = &gmT[c4 * 4][0] + lane;
            float m0 = gcol[0], m1 = gcol[32], m2 = gcol[64], m3 = gcol[96];
            acc[0] += w0.x * m0 + w0.y * m1 + w0.z * m2 + w0.w * m3;
            acc[1] += w1.x * m0 + w1.y * m1 + w1.z * m2 + w1.w * m3;
            acc[2] += w2.x * m0 + w2.y * m1 + w2.z * m2 + w2.w * m3;
            acc[3] += w3.x * m0 + w3.y * m1 + w3.z * m2 + w3.w * m3;
        }
        #pragma unroll
        for (int hh = 0; hh < 4; hh++) {
            int h = h0 + hh * 8;
            if (h < C2) g_c1[(size_t)(bbase + lane) * C2 + h] = acc[hh];
        }
    } else {
        float* mvec = shm;
        int b = blk - 152;
        for (int c = tid; c < DF; c += 256)
            mvec[c] = g_meaning[b * DF + c];
        __syncthreads();

        const float* Wm = muWall + (size_t)p * DS * C2;
        for (int d = warp; d < DS; d += 8) {
            float acc = 0.f;
            const float* r = Wm + (size_t)d * C2 + DF;
            for (int c = lane; c < DF; c += 32) acc += r[c] * mvec[c];
            acc = warp_red(acc);
            if (lane == 0) g_cmu[b * DS + d] = acc;
        }
        if (warp == 0) {
            const float* gw = gWall + p * C2 + DF;
            float acc = 0.f;
            for (int c = lane; c < DF; c += 32) acc += gw[c] * mvec[c];
            acc = warp_red(acc);
            if (lane == 0) g_cgate[b] = acc;
        }
        if (warp == 1) {
            float s1 = 0.f, s2 = 0.f;
            for (int c = lane; c < DF; c += 32) { float v = mvec[c]; s1 += v; s2 += v * v; }
            s1 = warp_red(s1); s2 = warp_red(s2);
            if (lane == 0) { g_csum[b] = s1; g_csum2[b] = s2; }
        }
    }
}

// ---------------- K4: refinement — fused load/LN, balanced GEMM2 ----------------
__global__ void __launch_bounds__(THR, 1) k_refine(int p,
    const float* __restrict__ mubAll,
    const float* __restrict__ gWall, const float* __restrict__ gbAll,
    const float* __restrict__ b2All)
{
    extern __shared__ float sm[];
    float* sX   = sm + OFF_X;
    float* sC1  = sm + OFF_SC1;
    float* sU1  = sm + OFF_SU1;
    float* sV1  = sm + OFF_SV1;
    float* sBmu = sm + OFF_SBMU;
    float* sB2  = sm + OFF_SB2;
    float* sA   = sm + OFF_SA;
    float* sM2  = sm + OFF_SM2;

    int b   = blockIdx.y;
    int s0  = blockIdx.x * T_TOK;
    int tid = threadIdx.x;
    int tokBase = b * SS + s0;
    int w = tid >> 5, lane = tid & 31;
    int kq = lane & 3, rq = lane >> 2;

    const float* w1src = g_W1f + (size_t)p * W1SZ;
    const float* w2src = g_W2f + (size_t)p * W2SZ;

    uint32_t smem_u32 = (uint32_t)__cvta_generic_to_shared(sm);
    uint32_t w1_u32[2] = { smem_u32 + OFF_W1A * 4, smem_u32 + OFF_W1B * 4 };
    uint32_t w2_u32[2] = { smem_u32 + OFF_SW2 * 4, smem_u32 + (OFF_SW2 + PAN2) * 4 };
    uint32_t mb = smem_u32 + OFF_MBAR * 4;

    if (tid == 0) {
        #pragma unroll
        for (int i = 0; i < 4; i++) MBAR_INIT(mb + 8 * i, 1);
        asm volatile("fence.proxy.async.shared::cta;" ::: "memory");
    }
    __syncthreads();

    if (tid == 0) {
        MBAR_EXPECT_TX(mb, SZP1);
        BULK_CP(w1_u32[0], w1src, SZP1, mb);
    }

    for (int i = tid; i < C2; i += THR) {
        sC1[i] = g_c1[b * C2 + i];
        sU1[i] = g_u1[p * C2 + i];
        sV1[i] = g_v1[p * C2 + i];
    }
    if (tid < DS)  sBmu[tid] = mubAll[p * DS + tid] + g_cmu[b * DS + tid];
    if (tid >= THR - DF) sB2[tid - (THR - DF)] = b2All[p * DF + (tid - (THR - DF))];

    // ---- fused: feature load (tf32 -> frag layout) + LN stats + alpha gate ----
    {
        float csum = g_csum[b], csum2 = g_csum2[b], cgate = g_cgate[b];
        const float* gw = gWall + p * C2;
        float gbv = gbAll[p];
        #pragma unroll
        for (int tt = 0; tt < 4; tt++) {
            int t = w * 4 + tt;
            const float* fp = g_feat + (size_t)(tokBase + t) * DF;
            float s1 = 0.f, s2 = 0.f, gd = 0.f;
            for (int f = lane; f < DF; f += 32) {
                float v = fp[f];
                s1 += v; s2 += v * v; gd += gw[f] * v;
                sX[frag_addr(f, t)] = tf32r(v);
            }
            s1 = warp_red(s1); s2 = warp_red(s2); gd = warp_red(gd);
            if (lane == 0) {
                float mean = (s1 + csum) * (1.0f / C2);
                float var  = (s2 + csum2) * (1.0f / C2) - mean * mean;
                float rstd = rsqrtf(var + 1e-5f);
                sA[t]  = rstd;
                sM2[t] = -mean * rstd;
                g_alpha[tokBase + t] *= sigmoidf_(gd + cgate + gbv);
            }
        }
    }
    // zero K-pad sub-elements of kstep 37 (k = 300..303 -> odd-e positions)
    if (tid < 256)
        sX[37 * 512 + (tid >> 1) * 4 + ((tid & 1) << 1) + 1] = 0.f;
    __syncthreads();

    // ================= GEMM1: [672 x 304] @ [304 x 64], 19 x 16-k panels =================
    float acc[3][32];
    #pragma unroll
    for (int i = 0; i < 3; i++)
        #pragma unroll
        for (int j = 0; j < 32; j++) acc[i][j] = 0.f;

    for (int s = 0; s < NP1; s++) {
        __syncthreads();
        if (tid == 0 && s + 1 < NP1) {
            uint32_t m = mb + 8 * ((s + 1) & 1);
            MBAR_EXPECT_TX(m, SZP1);
            BULK_CP(w1_u32[(s + 1) & 1], w1src + (size_t)(s + 1) * PAN1, SZP1, m);
        }
        mbar_wait(mb + 8 * (s & 1), (s >> 1) & 1);

        const float* swp = sm + ((s & 1) ? OFF_W1B : OFF_W1A);
        #pragma unroll
        for (int sub = 0; sub < 2; sub++) {
            const float* swb = swp + sub * (NT1 * 128);
            const uint4* bp = (const uint4*)(sX + (s * 2 + sub) * 512) + lane;
            uint4 u0 = bp[0], u1 = bp[32], u2 = bp[64], u3 = bp[96];
            #pragma unroll
            for (int i = 0; i < 3; i++) {
                int tile = w + NWARP * i;
                if (tile < NT1) {
                    uint4 aa = *(const uint4*)(swb + tile * 128 + lane * 4);
                    mma_tf32(&acc[i][0],  aa, u0.x, u0.y);
                    mma_tf32(&acc[i][4],  aa, u0.z, u0.w);
                    mma_tf32(&acc[i][8],  aa, u1.x, u1.y);
                    mma_tf32(&acc[i][12], aa, u1.z, u1.w);
                    mma_tf32(&acc[i][16], aa, u2.x, u2.y);
                    mma_tf32(&acc[i][20], aa, u2.z, u2.w);
                    mma_tf32(&acc[i][24], aa, u3.x, u3.y);
                    mma_tf32(&acc[i][28], aa, u3.z, u3.w);
                }
            }
        }
    }
    __syncthreads();   // all GEMM1 reads done before epilogue rewrites sX

    // prefetch GEMM2 panel 0 (overlaps epilogue)
    if (tid == 0) {
        MBAR_EXPECT_TX(mb + 16, SZP2);
        BULK_CP(w2_u32[0], w2src, SZP2, mb + 16);
    }

    // ---- GEMM1 epilogue: LN/GELU -> sH fragments ; mu rows -> tanh -> g_mu ----
    #pragma unroll
    for (int i = 0; i < 3; i++) {
        int tile = w + NWARP * i;
        if (tile < NT1) {
            int m0 = tile * 16;
            #pragma unroll
            for (int half = 0; half < 2; half++) {
                int r = m0 + rq + half * 8;
                if (r < C2) {
                    float c1v = sC1[r], u1v = sU1[r], v1v = sV1[r];
                    #pragma unroll
                    for (int nb = 0; nb < 8; nb++)
                        #pragma unroll
                        for (int q = 0; q < 2; q++) {
                            int n = nb * 8 + 2 * kq + q;
                            float a = acc[i][nb * 4 + half * 2 + q];
                            float x = sA[n] * (a + c1v) + sM2[n] * u1v + v1v;
                            float gl = 0.5f * x * (1.0f + erff(x * 0.70710678118654752f));
                            sX[frag_addr(r, n)] = tf32r(gl);
                        }
                } else if (r < C2 + DS) {
                    int d = r - C2;
                    float bm = sBmu[d];
                    #pragma unroll
                    for (int nb = 0; nb < 8; nb++)
                        #pragma unroll
                        for (int q = 0; q < 2; q++) {
                            int n = nb * 8 + 2 * kq + q;
                            float a = acc[i][nb * 4 + half * 2 + q];
                            g_mu[(size_t)(tokBase + n) * DS + d] += tanhf(a + bm);
                        }
                }
            }
        }
    }
    // zero K-pad kstep 75 (rows 600..607) of sH fragments
    if (tid < 512) sX[75 * 512 + tid] = 0.f;
    __syncthreads();   // sH (incl. pad) fully written before GEMM2 reads

    // ================= GEMM2: [304 x 608] @ [608 x 64], N-split units =================
    // unit = (tile, h): 38 units of m16n32; h = w&1 is warp-constant.
    float ac2[3][16];
    #pragma unroll
    for (int i = 0; i < 3; i++)
        #pragma unroll
        for (int j = 0; j < 16; j++) ac2[i][j] = 0.f;

    int h2 = w & 1;
    int t2b = w >> 1;

    for (int s = 0; s < NP2; s++) {
        __syncthreads();
        if (tid == 0 && s + 1 < NP2) {
            uint32_t m = mb + 16 + 8 * ((s + 1) & 1);
            MBAR_EXPECT_TX(m, SZP2);
            BULK_CP(w2_u32[(s + 1) & 1], w2src + (size_t)(s + 1) * PAN2, SZP2, m);
        }
        mbar_wait(mb + 16 + 8 * (s & 1), (s >> 1) & 1);

        const float* swp = sm + OFF_SW2 + (s & 1) * PAN2;
        #pragma unroll
        for (int sub = 0; sub < 2; sub++) {
            const float* swb = swp + sub * (NT2 * 128);
            const uint4* bp = (const uint4*)(sX + (s * 2 + sub) * 512) + lane + h2 * 64;
            uint4 v0 = bp[0], v1 = bp[32];
            #pragma unroll
            for (int i = 0; i < 3; i++) {
                if (w + NWARP * i < 38) {
                    int tile = t2b + 8 * i;
                    uint4 aa = *(const uint4*)(swb + tile * 128 + lane * 4);
                    mma_tf32(&ac2[i][0],  aa, v0.x, v0.y);
                    mma_tf32(&ac2[i][4],  aa, v0.z, v0.w);
                    mma_tf32(&ac2[i][8],  aa, v1.x, v1.y);
                    mma_tf32(&ac2[i][12], aa, v1.z, v1.w);
                }
            }
        }
    }
    __syncthreads();

    // ---- stage dfeat into sX[f*LDB1+n] (sH dead) ----
    #pragma unroll
    for (int i = 0; i < 3; i++) {
        if (w + NWARP * i < 38) {
            int tile = t2b + 8 * i;
            int m0 = tile * 16;
            #pragma unroll
            for (int half = 0; half < 2; half++) {
                int f = m0 + rq + half * 8;
                if (f < DF) {
                    #pragma unroll
                    for (int nb = 0; nb < 4; nb++)
                        #pragma unroll
                        for (int q = 0; q < 2; q++) {
                            int n = h2 * 32 + nb * 8 + 2 * kq + q;
                            sX[f * LDB1 + n] = ac2[i][nb * 4 + half * 2 + q];
                        }
                }
            }
        }
    }
    __syncthreads();

    // ---- coalesced residual writeback ----
    for (int idx = tid; idx < DF * T_TOK; idx += THR) {
        int t = idx / DF;
        int f = idx - t * DF;
        size_t a = (size_t)(tokBase + t) * DF + f;
        g_feat[a] = g_feat[a] + sX[f * LDB1 + t] + sB2[f];
    }
}

// ---------------- host launch ----------------
// Launch order: init+prep(1), render(2), ctx(3), refine p0 (4) <- profiled.
extern "C" void kernel_launch(void* const* d_in, const int* in_sizes, int n_in,
                              void* d_out, int out_size)
{
    const int*   ids     = (const int*)  d_in[0];
    const float* mu_t    = (const float*)d_in[2];
    const float* lv_t    = (const float*)d_in[3];
    const float* a_t     = (const float*)d_in[4];
    const float* f_t     = (const float*)d_in[5];
    const float* log_tau = (const float*)d_in[6];
    const float* pos_mu  = (const float*)d_in[7];
    const float* pos_a   = (const float*)d_in[8];
    const float* muW     = (const float*)d_in[9];
    const float* mub     = (const float*)d_in[10];
    const float* gW      = (const float*)d_in[11];
    const float* gb      = (const float*)d_in[12];
    const float* lng     = (const float*)d_in[13];
    const float* lnb     = (const float*)d_in[14];
    const float* W1      = (const float*)d_in[15];
    const float* b1      = (const float*)d_in[16];
    const float* W2      = (const float*)d_in[17];
    const float* b2      = (const float*)d_in[18];
    float* out = (float*)d_out;

    cudaFuncSetAttribute(k_refine, cudaFuncAttributeMaxDynamicSharedMemorySize, SMEM_BYTES);

    // one launch: token init + all 3 passes' weight fragments + u1/v1
    k_init_prep<<<NTOK + 3 * NPREP + 3 * C2, 128>>>(
        ids, mu_t, lv_t, a_t, f_t, pos_mu, pos_a, W1, lng, lnb, b1, muW, W2);

    dim3 grid(SS / T_TOK, BB);
    for (int p = 0; p < NPASS - 1; p++) {
        k_render<<<BB, 512>>>(log_tau, out, 0);
        k_ctx<<<408, 256>>>(p, W1, lng, muW, gW);
        k_refine<<<grid, THR, SMEM_BYTES>>>(p, mub, gW, gb, b2);
    }
    k_render<<<BB, 512>>>(log_tau, out, 1);
}